// round 4
// baseline (speedup 1.0000x reference)
#include <cuda_runtime.h>

#define N_NODES 50000
#define N_EDGES 800000
#define HDIM    64
#define NCLS    6
#define NGRAPH  500
#define BN_EPS  1e-5f
#define SCAN_T  1024

// ---------------- scratch (allocation-free: __device__ globals) -------------
__device__ __align__(16) float d_t[N_NODES * HDIM];     // post-GEMM features
__device__ __align__(16) float d_agg[N_NODES * HDIM];   // aggregated features
__device__ int   d_cnt_e[N_NODES];          // in-edge counts
__device__ int   d_off[N_NODES + 1];        // CSR offsets
__device__ int   d_pos[N_NODES];            // scatter cursors
__device__ int   d_csr_src[N_EDGES];        // CSR src ids
__device__ float d_csr_w[N_EDGES];          // CSR edge weights (norm)
__device__ float d_dinv[N_NODES];
__device__ float d_sum[HDIM];
__device__ float d_sq[HDIM];
__device__ __align__(16) float d_a[HDIM];   // BN scale
__device__ __align__(16) float d_c[HDIM];   // BN shift (bias folded in)
__device__ __align__(16) float d_pool[NGRAPH * HDIM];
__device__ float d_gcnt[NGRAPH];

// ---------------- CSR build ---------------------------------------------------
__global__ void k_zero_counts() {
    int i = blockIdx.x * blockDim.x + threadIdx.x;
    if (i < N_NODES) d_cnt_e[i] = 0;
}

__global__ void k_hist(const int* __restrict__ dst) {
    int e = blockIdx.x * blockDim.x + threadIdx.x;
    if (e < N_EDGES) atomicAdd(&d_cnt_e[dst[e]], 1);
}

// single-block exclusive scan; also emits pos cursors and dinv = rsqrt(cnt+1)
__global__ __launch_bounds__(SCAN_T) void k_scan() {
    const int CH = (N_NODES + SCAN_T - 1) / SCAN_T;
    int tid = threadIdx.x;
    int beg = tid * CH;
    int end = min(beg + CH, N_NODES);
    int s = 0;
    for (int i = beg; i < end; i++) s += d_cnt_e[i];
    __shared__ int part[SCAN_T];
    part[tid] = s;
    __syncthreads();
    for (int st = 1; st < SCAN_T; st <<= 1) {
        int v = (tid >= st) ? part[tid - st] : 0;
        __syncthreads();
        part[tid] += v;
        __syncthreads();
    }
    int run = (tid > 0) ? part[tid - 1] : 0;
    for (int i = beg; i < end; i++) {
        int c = d_cnt_e[i];
        d_off[i] = run;
        d_pos[i] = run;
        d_dinv[i] = rsqrtf((float)(c + 1));
        run += c;
    }
    if (tid == SCAN_T - 1) d_off[N_NODES] = run;
}

__global__ void k_scatter(const int* __restrict__ src, const int* __restrict__ dst) {
    int e = blockIdx.x * blockDim.x + threadIdx.x;
    if (e >= N_EDGES) return;
    int s = src[e], d = dst[e];
    float w = d_dinv[s] * d_dinv[d];
    int p = atomicAdd(&d_pos[d], 1);
    d_csr_src[p] = s;
    d_csr_w[p] = w;
}

// ---------------- fused GEMM ---------------------------------------------------
// Y[N,64] = act(X)[N,64] @ W[64,64]; act = identity (layer 0) or BN-affine+ReLU.
// X selected in device code: external input (layer 0) or d_agg (layers 1,2).
// Writes d_t only; self-loop handled by k_aggregate.
__global__ __launch_bounds__(256) void k_gemm(const float* __restrict__ Xext,
                                              const float* __restrict__ W,
                                              int apply_bn) {
    __shared__ float Xs[64][68];
    __shared__ float Ws[64][68];

    const float* X = apply_bn ? (const float*)d_agg : Xext;

    int tid = threadIdx.x;
    int tx = tid & 15;             // col group (4 cols)
    int ty = tid >> 4;             // row group (4 rows)
    int base = blockIdx.x * 64;

    if (blockIdx.x == 0 && tid < 64) { d_sum[tid] = 0.0f; d_sq[tid] = 0.0f; }

    // stage W[k][c]
    {
        int k = tid >> 4, cg = tid & 15;
#pragma unroll
        for (int i = 0; i < 4; i++) {
            float4 w = ((const float4*)W)[(k + i * 16) * 16 + cg];
            *(float4*)&Ws[k + i * 16][cg * 4] = w;
        }
    }

    // stage X tile with optional fused BN-affine + ReLU
    {
        int rl = tid >> 4, cg = tid & 15;
        float4 a4 = make_float4(0.f, 0.f, 0.f, 0.f);
        float4 c4 = make_float4(0.f, 0.f, 0.f, 0.f);
        if (apply_bn) {
            a4 = ((const float4*)d_a)[cg];
            c4 = ((const float4*)d_c)[cg];
        }
#pragma unroll
        for (int i = 0; i < 4; i++) {
            int row = base + rl + i * 16;
            float4 v = make_float4(0.f, 0.f, 0.f, 0.f);
            if (row < N_NODES) v = ((const float4*)X)[row * 16 + cg];
            if (apply_bn) {
                v.x = fmaxf(0.0f, fmaf(v.x, a4.x, c4.x));
                v.y = fmaxf(0.0f, fmaf(v.y, a4.y, c4.y));
                v.z = fmaxf(0.0f, fmaf(v.z, a4.z, c4.z));
                v.w = fmaxf(0.0f, fmaf(v.w, a4.w, c4.w));
            }
            *(float4*)&Xs[rl + i * 16][cg * 4] = v;
        }
    }
    __syncthreads();

    float acc[4][4];
#pragma unroll
    for (int i = 0; i < 4; i++)
#pragma unroll
        for (int j = 0; j < 4; j++) acc[i][j] = 0.0f;

#pragma unroll
    for (int k4 = 0; k4 < 16; k4++) {
        float4 x0 = *(const float4*)&Xs[ty * 4 + 0][k4 * 4];
        float4 x1 = *(const float4*)&Xs[ty * 4 + 1][k4 * 4];
        float4 x2 = *(const float4*)&Xs[ty * 4 + 2][k4 * 4];
        float4 x3 = *(const float4*)&Xs[ty * 4 + 3][k4 * 4];
#pragma unroll
        for (int kk = 0; kk < 4; kk++) {
            float4 w = *(const float4*)&Ws[k4 * 4 + kk][tx * 4];
            float s0 = ((const float*)&x0)[kk];
            float s1 = ((const float*)&x1)[kk];
            float s2 = ((const float*)&x2)[kk];
            float s3 = ((const float*)&x3)[kk];
            acc[0][0] = fmaf(s0, w.x, acc[0][0]); acc[0][1] = fmaf(s0, w.y, acc[0][1]);
            acc[0][2] = fmaf(s0, w.z, acc[0][2]); acc[0][3] = fmaf(s0, w.w, acc[0][3]);
            acc[1][0] = fmaf(s1, w.x, acc[1][0]); acc[1][1] = fmaf(s1, w.y, acc[1][1]);
            acc[1][2] = fmaf(s1, w.z, acc[1][2]); acc[1][3] = fmaf(s1, w.w, acc[1][3]);
            acc[2][0] = fmaf(s2, w.x, acc[2][0]); acc[2][1] = fmaf(s2, w.y, acc[2][1]);
            acc[2][2] = fmaf(s2, w.z, acc[2][2]); acc[2][3] = fmaf(s2, w.w, acc[2][3]);
            acc[3][0] = fmaf(s3, w.x, acc[3][0]); acc[3][1] = fmaf(s3, w.y, acc[3][1]);
            acc[3][2] = fmaf(s3, w.z, acc[3][2]); acc[3][3] = fmaf(s3, w.w, acc[3][3]);
        }
    }

#pragma unroll
    for (int i = 0; i < 4; i++) {
        int row = base + ty * 4 + i;
        if (row < N_NODES) {
            float4 t = make_float4(acc[i][0], acc[i][1], acc[i][2], acc[i][3]);
            ((float4*)d_t)[row * 16 + tx] = t;
        }
    }
}

// ---------------- CSR segment-reduce aggregation ------------------------------
// One warp per node: agg[n] = dinv[n]^2 * t[n] + sum_{e in seg(n)} w_e * t[src_e]
__global__ __launch_bounds__(256) void k_aggregate() {
    int wid = threadIdx.x >> 5;        // 0..7
    int lane = threadIdx.x & 31;
    int node = blockIdx.x * 8 + wid;   // N divisible by 8

    int beg = d_off[node];
    int end = d_off[node + 1];
    float dv = d_dinv[node];
    float sw = dv * dv;

    const float2* t2 = (const float2*)d_t;
    float2 acc = t2[node * 32 + lane];
    acc.x *= sw; acc.y *= sw;

    for (int j0 = beg; j0 < end; j0 += 32) {
        int j = j0 + lane;
        int s = 0; float w = 0.0f;
        if (j < end) { s = __ldg(&d_csr_src[j]); w = __ldg(&d_csr_w[j]); }
        int cnt = min(32, end - j0);
        for (int t = 0; t < cnt; t++) {
            int   ss = __shfl_sync(0xffffffffu, s, t);
            float ww = __shfl_sync(0xffffffffu, w, t);
            float2 v = t2[ss * 32 + lane];
            acc.x = fmaf(ww, v.x, acc.x);
            acc.y = fmaf(ww, v.y, acc.y);
        }
    }
    ((float2*)d_agg)[node * 32 + lane] = acc;
}

// ---------------- BatchNorm statistics (vectorized) ---------------------------
__global__ __launch_bounds__(256) void k_stats(const float* __restrict__ b) {
    int tid = threadIdx.x;
    int cg = tid & 15;
    float4 bb = ((const float4*)b)[cg];
    float4 s = make_float4(0.f, 0.f, 0.f, 0.f);
    float4 s2 = make_float4(0.f, 0.f, 0.f, 0.f);
    for (int row = blockIdx.x * 16 + (tid >> 4); row < N_NODES; row += gridDim.x * 16) {
        float4 v = ((const float4*)d_agg)[row * 16 + cg];
        v.x += bb.x; v.y += bb.y; v.z += bb.z; v.w += bb.w;
        s.x += v.x; s.y += v.y; s.z += v.z; s.w += v.w;
        s2.x += v.x * v.x; s2.y += v.y * v.y; s2.z += v.z * v.z; s2.w += v.w * v.w;
    }
    __shared__ float sh[256 * 4], sh2[256 * 4];
    *(float4*)&sh[tid * 4] = s;
    *(float4*)&sh2[tid * 4] = s2;
    __syncthreads();
    if (tid < 64) {
        int cgc = tid >> 2, j = tid & 3;
        float a = 0.f, a2 = 0.f;
#pragma unroll
        for (int rt = 0; rt < 16; rt++) {
            a  += sh[(rt * 16 + cgc) * 4 + j];
            a2 += sh2[(rt * 16 + cgc) * 4 + j];
        }
        atomicAdd(&d_sum[tid], a);
        atomicAdd(&d_sq[tid], a2);
    }
}

// fold mean/var/gamma/beta/bias into per-channel affine (a, c)
__global__ void k_finalize(const float* __restrict__ g,
                           const float* __restrict__ be,
                           const float* __restrict__ b) {
    int c = threadIdx.x;  // 64 threads
    float mu  = d_sum[c] * (1.0f / N_NODES);
    float var = d_sq[c] * (1.0f / N_NODES) - mu * mu;
    float inv = rsqrtf(var + BN_EPS);
    float a = __ldg(g + c) * inv;
    d_a[c] = a;
    d_c[c] = __ldg(be + c) + a * (__ldg(b + c) - mu);
}

// ---------------- pooling (fused BN+ReLU of layer 3) + classifier -------------
__global__ void k_pool_zero() {
    int i = blockIdx.x * blockDim.x + threadIdx.x;
    if (i < NGRAPH * HDIM) d_pool[i] = 0.0f;
    if (i < NGRAPH) d_gcnt[i] = 0.0f;
}

__global__ void k_pool(const int* __restrict__ batch) {
    int i = blockIdx.x * blockDim.x + threadIdx.x;   // N*16 chunks
    if (i >= N_NODES * 16) return;
    int node = i >> 4, c = i & 15;
    int g = __ldg(batch + node);
    float4 a4 = ((const float4*)d_a)[c];
    float4 c4 = ((const float4*)d_c)[c];
    float4 v = ((const float4*)d_agg)[i];
    v.x = fmaxf(0.0f, fmaf(v.x, a4.x, c4.x));
    v.y = fmaxf(0.0f, fmaf(v.y, a4.y, c4.y));
    v.z = fmaxf(0.0f, fmaf(v.z, a4.z, c4.z));
    v.w = fmaxf(0.0f, fmaf(v.w, a4.w, c4.w));
    float* p = d_pool + (g * 64 + c * 4);
    asm volatile("red.global.add.v4.f32 [%0], {%1,%2,%3,%4};"
                 :: "l"(p), "f"(v.x), "f"(v.y), "f"(v.z), "f"(v.w)
                 : "memory");
    if (c == 0) atomicAdd(&d_gcnt[g], 1.0f);
}

__global__ __launch_bounds__(64) void k_fc(const float* __restrict__ fcW,
                                           const float* __restrict__ fcb,
                                           float* __restrict__ out) {
    int g = blockIdx.x;
    int tid = threadIdx.x;  // 64
    __shared__ float p[64];
    float cnt = fmaxf(d_gcnt[g], 1.0f);
    p[tid] = d_pool[g * 64 + tid] / cnt;
    __syncthreads();
    if (tid < NCLS) {
        float acc = __ldg(fcb + tid);
#pragma unroll
        for (int k = 0; k < 64; k++)
            acc = fmaf(p[k], __ldg(fcW + k * NCLS + tid), acc);
        out[g * NCLS + tid] = acc;
    }
}

// ---------------- launch ------------------------------------------------------
extern "C" void kernel_launch(void* const* d_in, const int* in_sizes, int n_in,
                              void* d_out, int out_size) {
    const float* x     = (const float*)d_in[0];
    const int*   ei    = (const int*)d_in[1];
    const int*   src   = ei;              // edge_index[0]
    const int*   dst   = ei + N_EDGES;    // edge_index[1]
    const int*   batch = (const int*)d_in[2];
    const float* W[3]  = { (const float*)d_in[3],  (const float*)d_in[7],  (const float*)d_in[11] };
    const float* b[3]  = { (const float*)d_in[4],  (const float*)d_in[8],  (const float*)d_in[12] };
    const float* g[3]  = { (const float*)d_in[5],  (const float*)d_in[9],  (const float*)d_in[13] };
    const float* be[3] = { (const float*)d_in[6],  (const float*)d_in[10], (const float*)d_in[14] };
    const float* fcW   = (const float*)d_in[15];
    const float* fcb   = (const float*)d_in[16];
    float* out = (float*)d_out;

    // CSR build (once per call, reused by all 3 layers)
    k_zero_counts<<<(N_NODES + 255) / 256, 256>>>();
    k_hist<<<(N_EDGES + 255) / 256, 256>>>(dst);
    k_scan<<<1, SCAN_T>>>();
    k_scatter<<<(N_EDGES + 255) / 256, 256>>>(src, dst);

    const int gemm_grid = (N_NODES + 63) / 64;
    for (int l = 0; l < 3; l++) {
        k_gemm<<<gemm_grid, 256>>>(x, W[l], l == 0 ? 0 : 1);
        k_aggregate<<<N_NODES / 8, 256>>>();
        k_stats<<<256, 256>>>(b[l]);
        k_finalize<<<1, 64>>>(g[l], be[l], b[l]);
    }

    k_pool_zero<<<(NGRAPH * HDIM + 255) / 256, 256>>>();
    k_pool<<<(N_NODES * 16 + 255) / 256, 256>>>(batch);
    k_fc<<<NGRAPH, 64>>>(fcW, fcb, out);
}

// round 5
// speedup vs baseline: 1.3455x; 1.3455x over previous
#include <cuda_runtime.h>

#define N_NODES 50000
#define N_EDGES 800000
#define HDIM    64
#define NCLS    6
#define NGRAPH  500
#define BN_EPS  1e-5f
#define NBLK_SCAN ((N_NODES + 1023) / 1024)

// ---------------- scratch (allocation-free: __device__ globals) -------------
__device__ __align__(16) float d_t[N_NODES * HDIM];     // post-GEMM features
__device__ __align__(16) float d_agg[N_NODES * HDIM];   // aggregated features
__device__ int   d_cnt_e[N_NODES];          // in-edge counts
__device__ int   d_off[N_NODES + 1];        // CSR offsets
__device__ int   d_pos[N_NODES];            // scatter cursors
__device__ int   d_blk[NBLK_SCAN];          // scan block sums
__device__ int   d_csr_src[N_EDGES];        // CSR src ids
__device__ float d_csr_w[N_EDGES];          // CSR edge weights (norm)
__device__ float d_dinv[N_NODES];
__device__ float d_sum[HDIM];
__device__ float d_sq[HDIM];
__device__ __align__(16) float d_a[HDIM];   // BN scale
__device__ __align__(16) float d_c[HDIM];   // BN shift (bias folded in)
__device__ __align__(16) float d_pool[NGRAPH * HDIM];
__device__ float d_gcnt[NGRAPH];

// ---------------- CSR build ---------------------------------------------------
__global__ void k_zero_counts() {
    int i = blockIdx.x * blockDim.x + threadIdx.x;
    if (i < N_NODES) d_cnt_e[i] = 0;
}

__global__ void k_hist(const int* __restrict__ dst) {
    int e = blockIdx.x * blockDim.x + threadIdx.x;
    if (e < N_EDGES) atomicAdd(&d_cnt_e[dst[e]], 1);
}

// per-block inclusive scan (coalesced); emits exclusive-in-block offsets + dinv
__global__ __launch_bounds__(1024) void k_scan1() {
    __shared__ int sh[1024];
    int i = blockIdx.x * 1024 + threadIdx.x;
    int c = (i < N_NODES) ? d_cnt_e[i] : 0;
    sh[threadIdx.x] = c;
    __syncthreads();
#pragma unroll
    for (int st = 1; st < 1024; st <<= 1) {
        int v = (threadIdx.x >= st) ? sh[threadIdx.x - st] : 0;
        __syncthreads();
        sh[threadIdx.x] += v;
        __syncthreads();
    }
    if (i < N_NODES) {
        d_off[i] = sh[threadIdx.x] - c;          // exclusive within block
        d_dinv[i] = rsqrtf((float)(c + 1));
    }
    if (threadIdx.x == 1023) d_blk[blockIdx.x] = sh[1023];
}

__global__ void k_scan2() {
    if (threadIdx.x == 0) {
        int run = 0;
        for (int b = 0; b < NBLK_SCAN; b++) { int v = d_blk[b]; d_blk[b] = run; run += v; }
        d_off[N_NODES] = run;
    }
}

__global__ void k_scan3() {
    int i = blockIdx.x * blockDim.x + threadIdx.x;
    if (i < N_NODES) {
        int o = d_off[i] + d_blk[i >> 10];
        d_off[i] = o;
        d_pos[i] = o;
    }
}

__global__ void k_scatter(const int* __restrict__ src, const int* __restrict__ dst) {
    int e = blockIdx.x * blockDim.x + threadIdx.x;
    if (e >= N_EDGES) return;
    int s = src[e], d = dst[e];
    float w = d_dinv[s] * d_dinv[d];
    int p = atomicAdd(&d_pos[d], 1);
    d_csr_src[p] = s;
    d_csr_w[p] = w;
}

// ---------------- fused GEMM ---------------------------------------------------
// Y[N,64] = act(X)[N,64] @ W[64,64]; act = identity (layer 0) or BN-affine+ReLU.
// X selected in device code: external input (layer 0) or d_agg (layers 1,2).
__global__ __launch_bounds__(256) void k_gemm(const float* __restrict__ Xext,
                                              const float* __restrict__ W,
                                              int apply_bn) {
    __shared__ float Xs[64][68];
    __shared__ float Ws[64][68];

    const float* X = apply_bn ? (const float*)d_agg : Xext;

    int tid = threadIdx.x;
    int tx = tid & 15;             // col group (4 cols)
    int ty = tid >> 4;             // row group (4 rows)
    int base = blockIdx.x * 64;

    // zero BN stat accumulators for this layer (runs before k_aggregate)
    if (blockIdx.x == 0 && tid < 64) { d_sum[tid] = 0.0f; d_sq[tid] = 0.0f; }

    {
        int k = tid >> 4, cg = tid & 15;
#pragma unroll
        for (int i = 0; i < 4; i++) {
            float4 w = ((const float4*)W)[(k + i * 16) * 16 + cg];
            *(float4*)&Ws[k + i * 16][cg * 4] = w;
        }
    }
    {
        int rl = tid >> 4, cg = tid & 15;
        float4 a4 = make_float4(0.f, 0.f, 0.f, 0.f);
        float4 c4 = make_float4(0.f, 0.f, 0.f, 0.f);
        if (apply_bn) {
            a4 = ((const float4*)d_a)[cg];
            c4 = ((const float4*)d_c)[cg];
        }
#pragma unroll
        for (int i = 0; i < 4; i++) {
            int row = base + rl + i * 16;
            float4 v = make_float4(0.f, 0.f, 0.f, 0.f);
            if (row < N_NODES) v = ((const float4*)X)[row * 16 + cg];
            if (apply_bn) {
                v.x = fmaxf(0.0f, fmaf(v.x, a4.x, c4.x));
                v.y = fmaxf(0.0f, fmaf(v.y, a4.y, c4.y));
                v.z = fmaxf(0.0f, fmaf(v.z, a4.z, c4.z));
                v.w = fmaxf(0.0f, fmaf(v.w, a4.w, c4.w));
            }
            *(float4*)&Xs[rl + i * 16][cg * 4] = v;
        }
    }
    __syncthreads();

    float acc[4][4];
#pragma unroll
    for (int i = 0; i < 4; i++)
#pragma unroll
        for (int j = 0; j < 4; j++) acc[i][j] = 0.0f;

#pragma unroll
    for (int k4 = 0; k4 < 16; k4++) {
        float4 x0 = *(const float4*)&Xs[ty * 4 + 0][k4 * 4];
        float4 x1 = *(const float4*)&Xs[ty * 4 + 1][k4 * 4];
        float4 x2 = *(const float4*)&Xs[ty * 4 + 2][k4 * 4];
        float4 x3 = *(const float4*)&Xs[ty * 4 + 3][k4 * 4];
#pragma unroll
        for (int kk = 0; kk < 4; kk++) {
            float4 w = *(const float4*)&Ws[k4 * 4 + kk][tx * 4];
            float s0 = ((const float*)&x0)[kk];
            float s1 = ((const float*)&x1)[kk];
            float s2 = ((const float*)&x2)[kk];
            float s3 = ((const float*)&x3)[kk];
            acc[0][0] = fmaf(s0, w.x, acc[0][0]); acc[0][1] = fmaf(s0, w.y, acc[0][1]);
            acc[0][2] = fmaf(s0, w.z, acc[0][2]); acc[0][3] = fmaf(s0, w.w, acc[0][3]);
            acc[1][0] = fmaf(s1, w.x, acc[1][0]); acc[1][1] = fmaf(s1, w.y, acc[1][1]);
            acc[1][2] = fmaf(s1, w.z, acc[1][2]); acc[1][3] = fmaf(s1, w.w, acc[1][3]);
            acc[2][0] = fmaf(s2, w.x, acc[2][0]); acc[2][1] = fmaf(s2, w.y, acc[2][1]);
            acc[2][2] = fmaf(s2, w.z, acc[2][2]); acc[2][3] = fmaf(s2, w.w, acc[2][3]);
            acc[3][0] = fmaf(s3, w.x, acc[3][0]); acc[3][1] = fmaf(s3, w.y, acc[3][1]);
            acc[3][2] = fmaf(s3, w.z, acc[3][2]); acc[3][3] = fmaf(s3, w.w, acc[3][3]);
        }
    }

#pragma unroll
    for (int i = 0; i < 4; i++) {
        int row = base + ty * 4 + i;
        if (row < N_NODES) {
            float4 t = make_float4(acc[i][0], acc[i][1], acc[i][2], acc[i][3]);
            ((float4*)d_t)[row * 16 + tx] = t;
        }
    }
}

// ---------------- CSR pull aggregation + fused BN stats ------------------------
// One warp per node, lanes own 2 columns each; edges iterated together
// (idx/w loads broadcast), unroll-by-2 for gather MLP. Stats on (agg + bias)
// reduced in shared, one global atomic per block.
__global__ __launch_bounds__(256) void k_aggregate(const float* __restrict__ b) {
    int tid = threadIdx.x;
    int wid = tid >> 5;
    int lane = tid & 31;
    int node = blockIdx.x * 8 + wid;   // N divisible by 8

    __shared__ float sh_s[64], sh_q[64];
    if (tid < 64) { sh_s[tid] = 0.0f; sh_q[tid] = 0.0f; }
    __syncthreads();

    int beg = d_off[node];
    int end = d_off[node + 1];
    float dv = d_dinv[node];
    float sw = dv * dv;

    const float2* t2 = (const float2*)d_t;
    float2 acc = t2[node * 32 + lane];
    acc.x *= sw; acc.y *= sw;
    float2 acc2 = make_float2(0.0f, 0.0f);

    int j = beg;
    for (; j + 2 <= end; j += 2) {
        int   s0 = __ldg(&d_csr_src[j]);
        int   s1 = __ldg(&d_csr_src[j + 1]);
        float w0 = __ldg(&d_csr_w[j]);
        float w1 = __ldg(&d_csr_w[j + 1]);
        float2 v0 = t2[s0 * 32 + lane];
        float2 v1 = t2[s1 * 32 + lane];
        acc.x  = fmaf(w0, v0.x, acc.x);  acc.y  = fmaf(w0, v0.y, acc.y);
        acc2.x = fmaf(w1, v1.x, acc2.x); acc2.y = fmaf(w1, v1.y, acc2.y);
    }
    if (j < end) {
        int   s0 = __ldg(&d_csr_src[j]);
        float w0 = __ldg(&d_csr_w[j]);
        float2 v0 = t2[s0 * 32 + lane];
        acc.x = fmaf(w0, v0.x, acc.x); acc.y = fmaf(w0, v0.y, acc.y);
    }
    acc.x += acc2.x; acc.y += acc2.y;

    ((float2*)d_agg)[node * 32 + lane] = acc;

    // fused BN stats on (agg + bias)
    float bx = __ldg(b + lane * 2);
    float by = __ldg(b + lane * 2 + 1);
    float vx = acc.x + bx, vy = acc.y + by;
    atomicAdd(&sh_s[lane * 2], vx);
    atomicAdd(&sh_s[lane * 2 + 1], vy);
    atomicAdd(&sh_q[lane * 2], vx * vx);
    atomicAdd(&sh_q[lane * 2 + 1], vy * vy);
    __syncthreads();
    if (tid < 64) {
        atomicAdd(&d_sum[tid], sh_s[tid]);
        atomicAdd(&d_sq[tid], sh_q[tid]);
    }
}

// fold mean/var/gamma/beta/bias into per-channel affine (a, c)
__global__ void k_finalize(const float* __restrict__ g,
                           const float* __restrict__ be,
                           const float* __restrict__ b) {
    int c = threadIdx.x;  // 64 threads
    float mu  = d_sum[c] * (1.0f / N_NODES);
    float var = d_sq[c] * (1.0f / N_NODES) - mu * mu;
    float inv = rsqrtf(var + BN_EPS);
    float a = __ldg(g + c) * inv;
    d_a[c] = a;
    d_c[c] = __ldg(be + c) + a * (__ldg(b + c) - mu);
}

// ---------------- pooling (fused BN+ReLU of layer 3) + classifier -------------
__global__ void k_pool_zero() {
    int i = blockIdx.x * blockDim.x + threadIdx.x;
    if (i < NGRAPH * HDIM) d_pool[i] = 0.0f;
    if (i < NGRAPH) d_gcnt[i] = 0.0f;
}

__global__ void k_pool(const int* __restrict__ batch) {
    int i = blockIdx.x * blockDim.x + threadIdx.x;   // N*16 chunks
    if (i >= N_NODES * 16) return;
    int node = i >> 4, c = i & 15;
    int g = __ldg(batch + node);
    float4 a4 = ((const float4*)d_a)[c];
    float4 c4 = ((const float4*)d_c)[c];
    float4 v = ((const float4*)d_agg)[i];
    v.x = fmaxf(0.0f, fmaf(v.x, a4.x, c4.x));
    v.y = fmaxf(0.0f, fmaf(v.y, a4.y, c4.y));
    v.z = fmaxf(0.0f, fmaf(v.z, a4.z, c4.z));
    v.w = fmaxf(0.0f, fmaf(v.w, a4.w, c4.w));
    float* p = d_pool + (g * 64 + c * 4);
    asm volatile("red.global.add.v4.f32 [%0], {%1,%2,%3,%4};"
                 :: "l"(p), "f"(v.x), "f"(v.y), "f"(v.z), "f"(v.w)
                 : "memory");
    if (c == 0) atomicAdd(&d_gcnt[g], 1.0f);
}

__global__ __launch_bounds__(64) void k_fc(const float* __restrict__ fcW,
                                           const float* __restrict__ fcb,
                                           float* __restrict__ out) {
    int g = blockIdx.x;
    int tid = threadIdx.x;  // 64
    __shared__ float p[64];
    float cnt = fmaxf(d_gcnt[g], 1.0f);
    p[tid] = d_pool[g * 64 + tid] / cnt;
    __syncthreads();
    if (tid < NCLS) {
        float acc = __ldg(fcb + tid);
#pragma unroll
        for (int k = 0; k < 64; k++)
            acc = fmaf(p[k], __ldg(fcW + k * NCLS + tid), acc);
        out[g * NCLS + tid] = acc;
    }
}

// ---------------- launch ------------------------------------------------------
extern "C" void kernel_launch(void* const* d_in, const int* in_sizes, int n_in,
                              void* d_out, int out_size) {
    const float* x     = (const float*)d_in[0];
    const int*   ei    = (const int*)d_in[1];
    const int*   src   = ei;              // edge_index[0]
    const int*   dst   = ei + N_EDGES;    // edge_index[1]
    const int*   batch = (const int*)d_in[2];
    const float* W[3]  = { (const float*)d_in[3],  (const float*)d_in[7],  (const float*)d_in[11] };
    const float* b[3]  = { (const float*)d_in[4],  (const float*)d_in[8],  (const float*)d_in[12] };
    const float* g[3]  = { (const float*)d_in[5],  (const float*)d_in[9],  (const float*)d_in[13] };
    const float* be[3] = { (const float*)d_in[6],  (const float*)d_in[10], (const float*)d_in[14] };
    const float* fcW   = (const float*)d_in[15];
    const float* fcb   = (const float*)d_in[16];
    float* out = (float*)d_out;

    // CSR build (once per call, reused by all 3 layers)
    k_zero_counts<<<(N_NODES + 255) / 256, 256>>>();
    k_hist<<<(N_EDGES + 255) / 256, 256>>>(dst);
    k_scan1<<<NBLK_SCAN, 1024>>>();
    k_scan2<<<1, 32>>>();
    k_scan3<<<(N_NODES + 255) / 256, 256>>>();
    k_scatter<<<(N_EDGES + 255) / 256, 256>>>(src, dst);

    const int gemm_grid = (N_NODES + 63) / 64;
    for (int l = 0; l < 3; l++) {
        k_gemm<<<gemm_grid, 256>>>(x, W[l], l == 0 ? 0 : 1);
        k_aggregate<<<N_NODES / 8, 256>>>(b[l]);
        k_finalize<<<1, 64>>>(g[l], be[l], b[l]);
    }

    k_pool_zero<<<(NGRAPH * HDIM + 255) / 256, 256>>>();
    k_pool<<<(N_NODES * 16 + 255) / 256, 256>>>(batch);
    k_fc<<<NGRAPH, 64>>>(fcW, fcb, out);
}

// round 6
// speedup vs baseline: 1.4021x; 1.0421x over previous
#include <cuda_runtime.h>

#define N_NODES 50000
#define N_EDGES 800000
#define HDIM    64
#define NCLS    6
#define NGRAPH  500
#define BN_EPS  1e-5f
#define NBLK_SCAN ((N_NODES + 1023) / 1024)

// ---------------- scratch (allocation-free: __device__ globals) -------------
__device__ __align__(16) float d_t[N_NODES * HDIM];     // post-GEMM features
__device__ __align__(16) float d_agg[N_NODES * HDIM];   // aggregated features
__device__ int   d_cnt_e[N_NODES];          // in-edge counts
__device__ int   d_off[N_NODES + 1];        // CSR offsets
__device__ int   d_pos[N_NODES];            // scatter cursors
__device__ int   d_blk[NBLK_SCAN];          // scan block sums
__device__ int   d_csr_src[N_EDGES];        // CSR src ids
__device__ float d_csr_w[N_EDGES];          // CSR edge weights (norm)
__device__ float d_dinv[N_NODES];
__device__ float d_sumA[3 * HDIM];          // per-layer BN sum
__device__ float d_sqA[3 * HDIM];           // per-layer BN sumsq
__device__ __align__(16) float d_pool[NGRAPH * HDIM];
__device__ float d_gcnt[NGRAPH];

// ---------------- CSR build ---------------------------------------------------
__global__ void k_zero_counts() {
    int i = blockIdx.x * blockDim.x + threadIdx.x;
    if (i < N_NODES) d_cnt_e[i] = 0;
}

__global__ void k_hist(const int* __restrict__ dst) {
    int e = blockIdx.x * blockDim.x + threadIdx.x;
    if (e < N_EDGES) atomicAdd(&d_cnt_e[dst[e]], 1);
}

// per-block inclusive scan (coalesced); emits exclusive-in-block offsets + dinv
__global__ __launch_bounds__(1024) void k_scan1() {
    __shared__ int sh[1024];
    int i = blockIdx.x * 1024 + threadIdx.x;
    int c = (i < N_NODES) ? d_cnt_e[i] : 0;
    sh[threadIdx.x] = c;
    __syncthreads();
#pragma unroll
    for (int st = 1; st < 1024; st <<= 1) {
        int v = (threadIdx.x >= st) ? sh[threadIdx.x - st] : 0;
        __syncthreads();
        sh[threadIdx.x] += v;
        __syncthreads();
    }
    if (i < N_NODES) {
        d_off[i] = sh[threadIdx.x] - c;          // exclusive within block
        d_dinv[i] = rsqrtf((float)(c + 1));
    }
    if (threadIdx.x == 1023) d_blk[blockIdx.x] = sh[1023];
}

// parallel scan of the 49 block sums (one 64-thread block)
__global__ __launch_bounds__(64) void k_scan2() {
    __shared__ int sh[64];
    int t = threadIdx.x;
    int v = (t < NBLK_SCAN) ? d_blk[t] : 0;
    sh[t] = v;
    __syncthreads();
#pragma unroll
    for (int st = 1; st < 64; st <<= 1) {
        int u = (t >= st) ? sh[t - st] : 0;
        __syncthreads();
        sh[t] += u;
        __syncthreads();
    }
    if (t < NBLK_SCAN) d_blk[t] = sh[t] - v;     // exclusive
    if (t == NBLK_SCAN - 1) d_off[N_NODES] = sh[t];
}

// final offsets + cursors; also zero pool/gcnt and all per-layer BN stats
__global__ void k_scan3() {
    int i = blockIdx.x * blockDim.x + threadIdx.x;
    if (i < N_NODES) {
        int o = d_off[i] + d_blk[i >> 10];
        d_off[i] = o;
        d_pos[i] = o;
    }
    if (i < NGRAPH * HDIM) d_pool[i] = 0.0f;
    if (i < NGRAPH) d_gcnt[i] = 0.0f;
    if (i < 3 * HDIM) { d_sumA[i] = 0.0f; d_sqA[i] = 0.0f; }
}

__global__ void k_scatter(const int* __restrict__ src, const int* __restrict__ dst) {
    int e = blockIdx.x * blockDim.x + threadIdx.x;
    if (e >= N_EDGES) return;
    int s = src[e], d = dst[e];
    float w = d_dinv[s] * d_dinv[d];
    int p = atomicAdd(&d_pos[d], 1);
    d_csr_src[p] = s;
    d_csr_w[p] = w;
}

// ---------------- fused GEMM ---------------------------------------------------
// Y[N,64] = act(X)[N,64] @ W[64,64]; act = identity (layer 0) or BN-affine+ReLU
// computed inline from layer-(l-1) stats. X selected in device code.
__global__ __launch_bounds__(256) void k_gemm(const float* __restrict__ Xext,
                                              const float* __restrict__ W,
                                              const float* __restrict__ gp,
                                              const float* __restrict__ bep,
                                              const float* __restrict__ bp,
                                              int layer) {
    __shared__ float Xs[64][68];
    __shared__ float Ws[64][68];
    __shared__ __align__(16) float sh_a[64], sh_c[64];

    const int apply_bn = layer > 0;
    const float* X = apply_bn ? (const float*)d_agg : Xext;

    int tid = threadIdx.x;
    int tx = tid & 15;             // col group (4 cols)
    int ty = tid >> 4;             // row group (4 rows)
    int base = blockIdx.x * 64;

    // inline BN-affine fold from previous layer's stats
    if (apply_bn && tid < 64) {
        int o = (layer - 1) * 64 + tid;
        float mu  = d_sumA[o] * (1.0f / N_NODES);
        float var = d_sqA[o] * (1.0f / N_NODES) - mu * mu;
        float inv = rsqrtf(var + BN_EPS);
        float a = __ldg(gp + tid) * inv;
        sh_a[tid] = a;
        sh_c[tid] = __ldg(bep + tid) + a * (__ldg(bp + tid) - mu);
    }

    // stage W[k][c]
    {
        int k = tid >> 4, cg = tid & 15;
#pragma unroll
        for (int i = 0; i < 4; i++) {
            float4 w = ((const float4*)W)[(k + i * 16) * 16 + cg];
            *(float4*)&Ws[k + i * 16][cg * 4] = w;
        }
    }
    __syncthreads();

    // stage X tile with optional fused BN-affine + ReLU
    {
        int rl = tid >> 4, cg = tid & 15;
        float4 a4 = make_float4(0.f, 0.f, 0.f, 0.f);
        float4 c4 = make_float4(0.f, 0.f, 0.f, 0.f);
        if (apply_bn) {
            a4 = *(const float4*)&sh_a[cg * 4];
            c4 = *(const float4*)&sh_c[cg * 4];
        }
#pragma unroll
        for (int i = 0; i < 4; i++) {
            int row = base + rl + i * 16;
            float4 v = make_float4(0.f, 0.f, 0.f, 0.f);
            if (row < N_NODES) v = ((const float4*)X)[row * 16 + cg];
            if (apply_bn) {
                v.x = fmaxf(0.0f, fmaf(v.x, a4.x, c4.x));
                v.y = fmaxf(0.0f, fmaf(v.y, a4.y, c4.y));
                v.z = fmaxf(0.0f, fmaf(v.z, a4.z, c4.z));
                v.w = fmaxf(0.0f, fmaf(v.w, a4.w, c4.w));
            }
            *(float4*)&Xs[rl + i * 16][cg * 4] = v;
        }
    }
    __syncthreads();

    float acc[4][4];
#pragma unroll
    for (int i = 0; i < 4; i++)
#pragma unroll
        for (int j = 0; j < 4; j++) acc[i][j] = 0.0f;

#pragma unroll
    for (int k4 = 0; k4 < 16; k4++) {
        float4 x0 = *(const float4*)&Xs[ty * 4 + 0][k4 * 4];
        float4 x1 = *(const float4*)&Xs[ty * 4 + 1][k4 * 4];
        float4 x2 = *(const float4*)&Xs[ty * 4 + 2][k4 * 4];
        float4 x3 = *(const float4*)&Xs[ty * 4 + 3][k4 * 4];
#pragma unroll
        for (int kk = 0; kk < 4; kk++) {
            float4 w = *(const float4*)&Ws[k4 * 4 + kk][tx * 4];
            float s0 = ((const float*)&x0)[kk];
            float s1 = ((const float*)&x1)[kk];
            float s2 = ((const float*)&x2)[kk];
            float s3 = ((const float*)&x3)[kk];
            acc[0][0] = fmaf(s0, w.x, acc[0][0]); acc[0][1] = fmaf(s0, w.y, acc[0][1]);
            acc[0][2] = fmaf(s0, w.z, acc[0][2]); acc[0][3] = fmaf(s0, w.w, acc[0][3]);
            acc[1][0] = fmaf(s1, w.x, acc[1][0]); acc[1][1] = fmaf(s1, w.y, acc[1][1]);
            acc[1][2] = fmaf(s1, w.z, acc[1][2]); acc[1][3] = fmaf(s1, w.w, acc[1][3]);
            acc[2][0] = fmaf(s2, w.x, acc[2][0]); acc[2][1] = fmaf(s2, w.y, acc[2][1]);
            acc[2][2] = fmaf(s2, w.z, acc[2][2]); acc[2][3] = fmaf(s2, w.w, acc[2][3]);
            acc[3][0] = fmaf(s3, w.x, acc[3][0]); acc[3][1] = fmaf(s3, w.y, acc[3][1]);
            acc[3][2] = fmaf(s3, w.z, acc[3][2]); acc[3][3] = fmaf(s3, w.w, acc[3][3]);
        }
    }

#pragma unroll
    for (int i = 0; i < 4; i++) {
        int row = base + ty * 4 + i;
        if (row < N_NODES) {
            float4 t = make_float4(acc[i][0], acc[i][1], acc[i][2], acc[i][3]);
            ((float4*)d_t)[row * 16 + tx] = t;
        }
    }
}

// ---------------- CSR pull aggregation + fused BN stats ------------------------
// One warp per node, lanes own 2 columns; unroll-by-4 for gather MLP.
__global__ __launch_bounds__(256) void k_aggregate(const float* __restrict__ b,
                                                   int layer) {
    int tid = threadIdx.x;
    int wid = tid >> 5;
    int lane = tid & 31;
    int node = blockIdx.x * 8 + wid;   // N divisible by 8

    __shared__ float sh_s[64], sh_q[64];
    if (tid < 64) { sh_s[tid] = 0.0f; sh_q[tid] = 0.0f; }
    __syncthreads();

    int beg = d_off[node];
    int end = d_off[node + 1];
    float dv = d_dinv[node];
    float sw = dv * dv;

    const float2* t2 = (const float2*)d_t;
    float2 a0 = t2[node * 32 + lane];
    a0.x *= sw; a0.y *= sw;
    float2 a1 = make_float2(0.f, 0.f);
    float2 a2 = make_float2(0.f, 0.f);
    float2 a3 = make_float2(0.f, 0.f);

    int j = beg;
    for (; j + 4 <= end; j += 4) {
        int   s0 = __ldg(&d_csr_src[j]);
        int   s1 = __ldg(&d_csr_src[j + 1]);
        int   s2 = __ldg(&d_csr_src[j + 2]);
        int   s3 = __ldg(&d_csr_src[j + 3]);
        float w0 = __ldg(&d_csr_w[j]);
        float w1 = __ldg(&d_csr_w[j + 1]);
        float w2 = __ldg(&d_csr_w[j + 2]);
        float w3 = __ldg(&d_csr_w[j + 3]);
        float2 v0 = t2[s0 * 32 + lane];
        float2 v1 = t2[s1 * 32 + lane];
        float2 v2 = t2[s2 * 32 + lane];
        float2 v3 = t2[s3 * 32 + lane];
        a0.x = fmaf(w0, v0.x, a0.x); a0.y = fmaf(w0, v0.y, a0.y);
        a1.x = fmaf(w1, v1.x, a1.x); a1.y = fmaf(w1, v1.y, a1.y);
        a2.x = fmaf(w2, v2.x, a2.x); a2.y = fmaf(w2, v2.y, a2.y);
        a3.x = fmaf(w3, v3.x, a3.x); a3.y = fmaf(w3, v3.y, a3.y);
    }
    for (; j < end; j++) {
        int   s0 = __ldg(&d_csr_src[j]);
        float w0 = __ldg(&d_csr_w[j]);
        float2 v0 = t2[s0 * 32 + lane];
        a0.x = fmaf(w0, v0.x, a0.x); a0.y = fmaf(w0, v0.y, a0.y);
    }
    float2 acc;
    acc.x = (a0.x + a1.x) + (a2.x + a3.x);
    acc.y = (a0.y + a1.y) + (a2.y + a3.y);

    ((float2*)d_agg)[node * 32 + lane] = acc;

    // fused BN stats on (agg + bias)
    float bx = __ldg(b + lane * 2);
    float by = __ldg(b + lane * 2 + 1);
    float vx = acc.x + bx, vy = acc.y + by;
    atomicAdd(&sh_s[lane * 2], vx);
    atomicAdd(&sh_s[lane * 2 + 1], vy);
    atomicAdd(&sh_q[lane * 2], vx * vx);
    atomicAdd(&sh_q[lane * 2 + 1], vy * vy);
    __syncthreads();
    if (tid < 64) {
        atomicAdd(&d_sumA[layer * 64 + tid], sh_s[tid]);
        atomicAdd(&d_sqA[layer * 64 + tid], sh_q[tid]);
    }
}

// ---------------- pooling (fused BN+ReLU of layer 3) + classifier -------------
__global__ __launch_bounds__(256) void k_pool(const int* __restrict__ batch,
                                              const float* __restrict__ gp,
                                              const float* __restrict__ bep,
                                              const float* __restrict__ bp) {
    __shared__ __align__(16) float sh_a[64], sh_c[64];
    int tid = threadIdx.x;
    if (tid < 64) {
        int o = 2 * 64 + tid;
        float mu  = d_sumA[o] * (1.0f / N_NODES);
        float var = d_sqA[o] * (1.0f / N_NODES) - mu * mu;
        float inv = rsqrtf(var + BN_EPS);
        float a = __ldg(gp + tid) * inv;
        sh_a[tid] = a;
        sh_c[tid] = __ldg(bep + tid) + a * (__ldg(bp + tid) - mu);
    }
    __syncthreads();

    int i = blockIdx.x * blockDim.x + tid;   // N*16 chunks
    if (i >= N_NODES * 16) return;
    int node = i >> 4, c = i & 15;
    int g = __ldg(batch + node);
    float4 a4 = *(const float4*)&sh_a[c * 4];
    float4 c4 = *(const float4*)&sh_c[c * 4];
    float4 v = ((const float4*)d_agg)[i];
    v.x = fmaxf(0.0f, fmaf(v.x, a4.x, c4.x));
    v.y = fmaxf(0.0f, fmaf(v.y, a4.y, c4.y));
    v.z = fmaxf(0.0f, fmaf(v.z, a4.z, c4.z));
    v.w = fmaxf(0.0f, fmaf(v.w, a4.w, c4.w));
    float* p = d_pool + (g * 64 + c * 4);
    asm volatile("red.global.add.v4.f32 [%0], {%1,%2,%3,%4};"
                 :: "l"(p), "f"(v.x), "f"(v.y), "f"(v.z), "f"(v.w)
                 : "memory");
    if (c == 0) atomicAdd(&d_gcnt[g], 1.0f);
}

__global__ __launch_bounds__(64) void k_fc(const float* __restrict__ fcW,
                                           const float* __restrict__ fcb,
                                           float* __restrict__ out) {
    int g = blockIdx.x;
    int tid = threadIdx.x;  // 64
    __shared__ float p[64];
    float cnt = fmaxf(d_gcnt[g], 1.0f);
    p[tid] = d_pool[g * 64 + tid] / cnt;
    __syncthreads();
    if (tid < NCLS) {
        float acc = __ldg(fcb + tid);
#pragma unroll
        for (int k = 0; k < 64; k++)
            acc = fmaf(p[k], __ldg(fcW + k * NCLS + tid), acc);
        out[g * NCLS + tid] = acc;
    }
}

// ---------------- launch ------------------------------------------------------
extern "C" void kernel_launch(void* const* d_in, const int* in_sizes, int n_in,
                              void* d_out, int out_size) {
    const float* x     = (const float*)d_in[0];
    const int*   ei    = (const int*)d_in[1];
    const int*   src   = ei;              // edge_index[0]
    const int*   dst   = ei + N_EDGES;    // edge_index[1]
    const int*   batch = (const int*)d_in[2];
    const float* W[3]  = { (const float*)d_in[3],  (const float*)d_in[7],  (const float*)d_in[11] };
    const float* b[3]  = { (const float*)d_in[4],  (const float*)d_in[8],  (const float*)d_in[12] };
    const float* g[3]  = { (const float*)d_in[5],  (const float*)d_in[9],  (const float*)d_in[13] };
    const float* be[3] = { (const float*)d_in[6],  (const float*)d_in[10], (const float*)d_in[14] };
    const float* fcW   = (const float*)d_in[15];
    const float* fcb   = (const float*)d_in[16];
    float* out = (float*)d_out;

    // CSR build (once per call, reused by all 3 layers)
    k_zero_counts<<<(N_NODES + 255) / 256, 256>>>();
    k_hist<<<(N_EDGES + 255) / 256, 256>>>(dst);
    k_scan1<<<NBLK_SCAN, 1024>>>();
    k_scan2<<<1, 64>>>();
    k_scan3<<<(N_NODES + 255) / 256, 256>>>();
    k_scatter<<<(N_EDGES + 255) / 256, 256>>>(src, dst);

    const int gemm_grid = (N_NODES + 63) / 64;
    for (int l = 0; l < 3; l++) {
        const float* gp  = l > 0 ? g[l - 1]  : g[0];
        const float* bep = l > 0 ? be[l - 1] : be[0];
        const float* bp  = l > 0 ? b[l - 1]  : b[0];
        k_gemm<<<gemm_grid, 256>>>(x, W[l], gp, bep, bp, l);
        k_aggregate<<<N_NODES / 8, 256>>>(b[l], l);
    }

    k_pool<<<(N_NODES * 16 + 255) / 256, 256>>>(batch, g[2], be[2], b[2]);
    k_fc<<<NGRAPH, 64>>>(fcW, fcb, out);
}

// round 7
// speedup vs baseline: 1.4366x; 1.0246x over previous
#include <cuda_runtime.h>
#include <cuda_fp16.h>

#define N_NODES 50000
#define N_EDGES 800000
#define HDIM    64
#define NCLS    6
#define NGRAPH  500
#define BN_EPS  1e-5f
#define NBLK_SCAN ((N_NODES + 1023) / 1024)

// ---------------- scratch (allocation-free: __device__ globals) -------------
__device__ __align__(16) __half d_th[N_NODES * HDIM];   // post-GEMM features (fp16 storage)
__device__ __align__(16) float d_agg[N_NODES * HDIM];   // aggregated features (fp32)
__device__ int   d_cnt_e[N_NODES];          // in-edge counts
__device__ int   d_off[N_NODES + 1];        // CSR offsets
__device__ int   d_pos[N_NODES];            // scatter cursors
__device__ int   d_blk[NBLK_SCAN];          // scan block sums
__device__ int   d_csr_src[N_EDGES];        // CSR src ids
__device__ float d_csr_w[N_EDGES];          // CSR edge weights (norm)
__device__ float d_dinv[N_NODES];
__device__ float d_sumA[3 * HDIM];          // per-layer BN sum
__device__ float d_sqA[3 * HDIM];           // per-layer BN sumsq
__device__ __align__(16) float d_pool[NGRAPH * HDIM];
__device__ float d_gcnt[NGRAPH];

// ---------------- CSR build ---------------------------------------------------
__global__ void k_zero_counts() {
    int i = blockIdx.x * blockDim.x + threadIdx.x;
    if (i < N_NODES) d_cnt_e[i] = 0;
}

__global__ void k_hist(const int* __restrict__ dst) {
    int e = blockIdx.x * blockDim.x + threadIdx.x;
    if (e < N_EDGES) atomicAdd(&d_cnt_e[dst[e]], 1);
}

// per-block inclusive scan (coalesced); emits exclusive-in-block offsets + dinv
__global__ __launch_bounds__(1024) void k_scan1() {
    __shared__ int sh[1024];
    int i = blockIdx.x * 1024 + threadIdx.x;
    int c = (i < N_NODES) ? d_cnt_e[i] : 0;
    sh[threadIdx.x] = c;
    __syncthreads();
#pragma unroll
    for (int st = 1; st < 1024; st <<= 1) {
        int v = (threadIdx.x >= st) ? sh[threadIdx.x - st] : 0;
        __syncthreads();
        sh[threadIdx.x] += v;
        __syncthreads();
    }
    if (i < N_NODES) {
        d_off[i] = sh[threadIdx.x] - c;          // exclusive within block
        d_dinv[i] = rsqrtf((float)(c + 1));
    }
    if (threadIdx.x == 1023) d_blk[blockIdx.x] = sh[1023];
}

// final offsets + cursors; each block redundantly scans the 49 block sums in
// shared (removes the separate scan2 launch). Also zeroes pool/gcnt/BN stats.
__global__ __launch_bounds__(256) void k_scan3() {
    __shared__ int shv[64], shs[64];
    int t = threadIdx.x;
    if (t < 64) {
        int v = (t < NBLK_SCAN) ? d_blk[t] : 0;
        shv[t] = v;
        shs[t] = v;
    }
    __syncthreads();
#pragma unroll
    for (int st = 1; st < 64; st <<= 1) {
        int u = (t < 64 && t >= st) ? shs[t - st] : 0;
        __syncthreads();
        if (t < 64) shs[t] += u;
        __syncthreads();
    }

    int i = blockIdx.x * blockDim.x + t;
    if (i < N_NODES) {
        int bb = i >> 10;
        int ex = shs[bb] - shv[bb];              // exclusive prefix
        int o = d_off[i] + ex;
        d_off[i] = o;
        d_pos[i] = o;
    }
    if (blockIdx.x == 0 && t == 0) d_off[N_NODES] = shs[NBLK_SCAN - 1];
    if (i < NGRAPH * HDIM) d_pool[i] = 0.0f;
    if (i < NGRAPH) d_gcnt[i] = 0.0f;
    if (i < 3 * HDIM) { d_sumA[i] = 0.0f; d_sqA[i] = 0.0f; }
}

__global__ void k_scatter(const int* __restrict__ src, const int* __restrict__ dst) {
    int e = blockIdx.x * blockDim.x + threadIdx.x;
    if (e >= N_EDGES) return;
    int s = src[e], d = dst[e];
    float w = d_dinv[s] * d_dinv[d];
    int p = atomicAdd(&d_pos[d], 1);
    d_csr_src[p] = s;
    d_csr_w[p] = w;
}

// ---------------- fused GEMM ---------------------------------------------------
// Y[N,64] = act(X)[N,64] @ W[64,64]; act = identity (layer 0) or BN-affine+ReLU
// computed inline from layer-(l-1) stats. Output stored as fp16 (d_th).
__global__ __launch_bounds__(256) void k_gemm(const float* __restrict__ Xext,
                                              const float* __restrict__ W,
                                              const float* __restrict__ gp,
                                              const float* __restrict__ bep,
                                              const float* __restrict__ bp,
                                              int layer) {
    __shared__ float Xs[64][68];
    __shared__ float Ws[64][68];
    __shared__ __align__(16) float sh_a[64], sh_c[64];

    const int apply_bn = layer > 0;
    const float* X = apply_bn ? (const float*)d_agg : Xext;

    int tid = threadIdx.x;
    int tx = tid & 15;             // col group (4 cols)
    int ty = tid >> 4;             // row group (4 rows)
    int base = blockIdx.x * 64;

    // inline BN-affine fold from previous layer's stats
    if (apply_bn && tid < 64) {
        int o = (layer - 1) * 64 + tid;
        float mu  = d_sumA[o] * (1.0f / N_NODES);
        float var = d_sqA[o] * (1.0f / N_NODES) - mu * mu;
        float inv = rsqrtf(var + BN_EPS);
        float a = __ldg(gp + tid) * inv;
        sh_a[tid] = a;
        sh_c[tid] = __ldg(bep + tid) + a * (__ldg(bp + tid) - mu);
    }

    // stage W[k][c]
    {
        int k = tid >> 4, cg = tid & 15;
#pragma unroll
        for (int i = 0; i < 4; i++) {
            float4 w = ((const float4*)W)[(k + i * 16) * 16 + cg];
            *(float4*)&Ws[k + i * 16][cg * 4] = w;
        }
    }
    __syncthreads();

    // stage X tile with optional fused BN-affine + ReLU
    {
        int rl = tid >> 4, cg = tid & 15;
        float4 a4 = make_float4(0.f, 0.f, 0.f, 0.f);
        float4 c4 = make_float4(0.f, 0.f, 0.f, 0.f);
        if (apply_bn) {
            a4 = *(const float4*)&sh_a[cg * 4];
            c4 = *(const float4*)&sh_c[cg * 4];
        }
#pragma unroll
        for (int i = 0; i < 4; i++) {
            int row = base + rl + i * 16;
            float4 v = make_float4(0.f, 0.f, 0.f, 0.f);
            if (row < N_NODES) v = ((const float4*)X)[row * 16 + cg];
            if (apply_bn) {
                v.x = fmaxf(0.0f, fmaf(v.x, a4.x, c4.x));
                v.y = fmaxf(0.0f, fmaf(v.y, a4.y, c4.y));
                v.z = fmaxf(0.0f, fmaf(v.z, a4.z, c4.z));
                v.w = fmaxf(0.0f, fmaf(v.w, a4.w, c4.w));
            }
            *(float4*)&Xs[rl + i * 16][cg * 4] = v;
        }
    }
    __syncthreads();

    float acc[4][4];
#pragma unroll
    for (int i = 0; i < 4; i++)
#pragma unroll
        for (int j = 0; j < 4; j++) acc[i][j] = 0.0f;

#pragma unroll
    for (int k4 = 0; k4 < 16; k4++) {
        float4 x0 = *(const float4*)&Xs[ty * 4 + 0][k4 * 4];
        float4 x1 = *(const float4*)&Xs[ty * 4 + 1][k4 * 4];
        float4 x2 = *(const float4*)&Xs[ty * 4 + 2][k4 * 4];
        float4 x3 = *(const float4*)&Xs[ty * 4 + 3][k4 * 4];
#pragma unroll
        for (int kk = 0; kk < 4; kk++) {
            float4 w = *(const float4*)&Ws[k4 * 4 + kk][tx * 4];
            float s0 = ((const float*)&x0)[kk];
            float s1 = ((const float*)&x1)[kk];
            float s2 = ((const float*)&x2)[kk];
            float s3 = ((const float*)&x3)[kk];
            acc[0][0] = fmaf(s0, w.x, acc[0][0]); acc[0][1] = fmaf(s0, w.y, acc[0][1]);
            acc[0][2] = fmaf(s0, w.z, acc[0][2]); acc[0][3] = fmaf(s0, w.w, acc[0][3]);
            acc[1][0] = fmaf(s1, w.x, acc[1][0]); acc[1][1] = fmaf(s1, w.y, acc[1][1]);
            acc[1][2] = fmaf(s1, w.z, acc[1][2]); acc[1][3] = fmaf(s1, w.w, acc[1][3]);
            acc[2][0] = fmaf(s2, w.x, acc[2][0]); acc[2][1] = fmaf(s2, w.y, acc[2][1]);
            acc[2][2] = fmaf(s2, w.z, acc[2][2]); acc[2][3] = fmaf(s2, w.w, acc[2][3]);
            acc[3][0] = fmaf(s3, w.x, acc[3][0]); acc[3][1] = fmaf(s3, w.y, acc[3][1]);
            acc[3][2] = fmaf(s3, w.z, acc[3][2]); acc[3][3] = fmaf(s3, w.w, acc[3][3]);
        }
    }

    // epilogue: convert to fp16, 8-byte store per row (cols 4tx..4tx+3)
#pragma unroll
    for (int i = 0; i < 4; i++) {
        int row = base + ty * 4 + i;
        if (row < N_NODES) {
            __half2 h0 = __floats2half2_rn(acc[i][0], acc[i][1]);
            __half2 h1 = __floats2half2_rn(acc[i][2], acc[i][3]);
            uint2 pk;
            pk.x = *(unsigned int*)&h0;
            pk.y = *(unsigned int*)&h1;
            ((uint2*)d_th)[row * 16 + tx] = pk;
        }
    }
}

// ---------------- CSR pull aggregation + fused BN stats ------------------------
// One warp per node, lanes own 2 columns (one half2); unroll-by-4 gathers.
__global__ __launch_bounds__(256) void k_aggregate(const float* __restrict__ b,
                                                   int layer) {
    int tid = threadIdx.x;
    int wid = tid >> 5;
    int lane = tid & 31;
    int node = blockIdx.x * 8 + wid;   // N divisible by 8

    __shared__ float sh_s[64], sh_q[64];
    if (tid < 64) { sh_s[tid] = 0.0f; sh_q[tid] = 0.0f; }
    __syncthreads();

    int beg = d_off[node];
    int end = d_off[node + 1];
    float dv = d_dinv[node];
    float sw = dv * dv;

    const __half2* t2 = (const __half2*)d_th;
    float2 self = __half22float2(t2[node * 32 + lane]);
    float2 a0 = make_float2(self.x * sw, self.y * sw);
    float2 a1 = make_float2(0.f, 0.f);
    float2 a2 = make_float2(0.f, 0.f);
    float2 a3 = make_float2(0.f, 0.f);

    int j = beg;
    for (; j + 4 <= end; j += 4) {
        int   s0 = __ldg(&d_csr_src[j]);
        int   s1 = __ldg(&d_csr_src[j + 1]);
        int   s2 = __ldg(&d_csr_src[j + 2]);
        int   s3 = __ldg(&d_csr_src[j + 3]);
        float w0 = __ldg(&d_csr_w[j]);
        float w1 = __ldg(&d_csr_w[j + 1]);
        float w2 = __ldg(&d_csr_w[j + 2]);
        float w3 = __ldg(&d_csr_w[j + 3]);
        float2 v0 = __half22float2(t2[s0 * 32 + lane]);
        float2 v1 = __half22float2(t2[s1 * 32 + lane]);
        float2 v2 = __half22float2(t2[s2 * 32 + lane]);
        float2 v3 = __half22float2(t2[s3 * 32 + lane]);
        a0.x = fmaf(w0, v0.x, a0.x); a0.y = fmaf(w0, v0.y, a0.y);
        a1.x = fmaf(w1, v1.x, a1.x); a1.y = fmaf(w1, v1.y, a1.y);
        a2.x = fmaf(w2, v2.x, a2.x); a2.y = fmaf(w2, v2.y, a2.y);
        a3.x = fmaf(w3, v3.x, a3.x); a3.y = fmaf(w3, v3.y, a3.y);
    }
    for (; j < end; j++) {
        int   s0 = __ldg(&d_csr_src[j]);
        float w0 = __ldg(&d_csr_w[j]);
        float2 v0 = __half22float2(t2[s0 * 32 + lane]);
        a0.x = fmaf(w0, v0.x, a0.x); a0.y = fmaf(w0, v0.y, a0.y);
    }
    float2 acc;
    acc.x = (a0.x + a1.x) + (a2.x + a3.x);
    acc.y = (a0.y + a1.y) + (a2.y + a3.y);

    ((float2*)d_agg)[node * 32 + lane] = acc;

    // fused BN stats on (agg + bias)
    float bx = __ldg(b + lane * 2);
    float by = __ldg(b + lane * 2 + 1);
    float vx = acc.x + bx, vy = acc.y + by;
    atomicAdd(&sh_s[lane * 2], vx);
    atomicAdd(&sh_s[lane * 2 + 1], vy);
    atomicAdd(&sh_q[lane * 2], vx * vx);
    atomicAdd(&sh_q[lane * 2 + 1], vy * vy);
    __syncthreads();
    if (tid < 64) {
        atomicAdd(&d_sumA[layer * 64 + tid], sh_s[tid]);
        atomicAdd(&d_sqA[layer * 64 + tid], sh_q[tid]);
    }
}

// ---------------- pooling (fused BN+ReLU of layer 3) + classifier -------------
__global__ __launch_bounds__(256) void k_pool(const int* __restrict__ batch,
                                              const float* __restrict__ gp,
                                              const float* __restrict__ bep,
                                              const float* __restrict__ bp) {
    __shared__ __align__(16) float sh_a[64], sh_c[64];
    int tid = threadIdx.x;
    if (tid < 64) {
        int o = 2 * 64 + tid;
        float mu  = d_sumA[o] * (1.0f / N_NODES);
        float var = d_sqA[o] * (1.0f / N_NODES) - mu * mu;
        float inv = rsqrtf(var + BN_EPS);
        float a = __ldg(gp + tid) * inv;
        sh_a[tid] = a;
        sh_c[tid] = __ldg(bep + tid) + a * (__ldg(bp + tid) - mu);
    }
    __syncthreads();

    int i = blockIdx.x * blockDim.x + tid;   // N*16 chunks
    if (i >= N_NODES * 16) return;
    int node = i >> 4, c = i & 15;
    int g = __ldg(batch + node);
    float4 a4 = *(const float4*)&sh_a[c * 4];
    float4 c4 = *(const float4*)&sh_c[c * 4];
    float4 v = ((const float4*)d_agg)[i];
    v.x = fmaxf(0.0f, fmaf(v.x, a4.x, c4.x));
    v.y = fmaxf(0.0f, fmaf(v.y, a4.y, c4.y));
    v.z = fmaxf(0.0f, fmaf(v.z, a4.z, c4.z));
    v.w = fmaxf(0.0f, fmaf(v.w, a4.w, c4.w));
    float* p = d_pool + (g * 64 + c * 4);
    asm volatile("red.global.add.v4.f32 [%0], {%1,%2,%3,%4};"
                 :: "l"(p), "f"(v.x), "f"(v.y), "f"(v.z), "f"(v.w)
                 : "memory");
    if (c == 0) atomicAdd(&d_gcnt[g], 1.0f);
}

__global__ __launch_bounds__(64) void k_fc(const float* __restrict__ fcW,
                                           const float* __restrict__ fcb,
                                           float* __restrict__ out) {
    int g = blockIdx.x;
    int tid = threadIdx.x;  // 64
    __shared__ float p[64];
    float cnt = fmaxf(d_gcnt[g], 1.0f);
    p[tid] = d_pool[g * 64 + tid] / cnt;
    __syncthreads();
    if (tid < NCLS) {
        float acc = __ldg(fcb + tid);
#pragma unroll
        for (int k = 0; k < 64; k++)
            acc = fmaf(p[k], __ldg(fcW + k * NCLS + tid), acc);
        out[g * NCLS + tid] = acc;
    }
}

// ---------------- launch ------------------------------------------------------
extern "C" void kernel_launch(void* const* d_in, const int* in_sizes, int n_in,
                              void* d_out, int out_size) {
    const float* x     = (const float*)d_in[0];
    const int*   ei    = (const int*)d_in[1];
    const int*   src   = ei;              // edge_index[0]
    const int*   dst   = ei + N_EDGES;    // edge_index[1]
    const int*   batch = (const int*)d_in[2];
    const float* W[3]  = { (const float*)d_in[3],  (const float*)d_in[7],  (const float*)d_in[11] };
    const float* b[3]  = { (const float*)d_in[4],  (const float*)d_in[8],  (const float*)d_in[12] };
    const float* g[3]  = { (const float*)d_in[5],  (const float*)d_in[9],  (const float*)d_in[13] };
    const float* be[3] = { (const float*)d_in[6],  (const float*)d_in[10], (const float*)d_in[14] };
    const float* fcW   = (const float*)d_in[15];
    const float* fcb   = (const float*)d_in[16];
    float* out = (float*)d_out;

    // CSR build (once per call, reused by all 3 layers)
    k_zero_counts<<<(N_NODES + 255) / 256, 256>>>();
    k_hist<<<(N_EDGES + 255) / 256, 256>>>(dst);
    k_scan1<<<NBLK_SCAN, 1024>>>();
    k_scan3<<<(N_NODES + 255) / 256, 256>>>();
    k_scatter<<<(N_EDGES + 255) / 256, 256>>>(src, dst);

    const int gemm_grid = (N_NODES + 63) / 64;
    for (int l = 0; l < 3; l++) {
        const float* gp  = l > 0 ? g[l - 1]  : g[0];
        const float* bep = l > 0 ? be[l - 1] : be[0];
        const float* bp  = l > 0 ? b[l - 1]  : b[0];
        k_gemm<<<gemm_grid, 256>>>(x, W[l], gp, bep, bp, l);
        k_aggregate<<<N_NODES / 8, 256>>>(b[l], l);
    }

    k_pool<<<(N_NODES * 16 + 255) / 256, 256>>>(batch, g[2], be[2], b[2]);
    k_fc<<<NGRAPH, 64>>>(fcW, fcb, out);
}

// round 8
// speedup vs baseline: 1.6805x; 1.1697x over previous
#include <cuda_runtime.h>
#include <cuda_fp16.h>

#define N_NODES 50000
#define N_EDGES 800000
#define HDIM    64
#define NCLS    6
#define NGRAPH  500
#define BN_EPS  1e-5f
#define NBLK_SCAN ((N_NODES + 1023) / 1024)
#define NPW     8   // nodes per warp in aggregation

// ---------------- scratch (allocation-free: __device__ globals) -------------
__device__ __align__(16) __half d_th[N_NODES * HDIM];   // post-GEMM features (fp16)
__device__ __align__(16) float d_agg[N_NODES * HDIM];   // aggregated features (fp32)
__device__ int   d_cnt_e[N_NODES];          // in-edge counts
__device__ int   d_off[N_NODES + 1];        // CSR offsets
__device__ int   d_pos[N_NODES];            // scatter cursors
__device__ int   d_blk[NBLK_SCAN];          // scan block sums
__device__ __align__(8) int2 d_csr[N_EDGES];  // CSR packed (src, w bits)
__device__ float d_dinv[N_NODES];
__device__ float d_sumA[3 * HDIM];          // per-layer BN sum
__device__ float d_sqA[3 * HDIM];           // per-layer BN sumsq
__device__ __align__(16) float d_pool[NGRAPH * HDIM];
__device__ float d_gcnt[NGRAPH];

// ---------------- CSR build ---------------------------------------------------
__global__ void k_zero_counts() {
    int i = blockIdx.x * blockDim.x + threadIdx.x;
    if (i < N_NODES) d_cnt_e[i] = 0;
}

__global__ void k_hist(const int* __restrict__ dst) {
    int e = blockIdx.x * blockDim.x + threadIdx.x;
    if (e < N_EDGES) atomicAdd(&d_cnt_e[dst[e]], 1);
}

// per-block inclusive scan (coalesced); emits exclusive-in-block offsets + dinv
__global__ __launch_bounds__(1024) void k_scan1() {
    __shared__ int sh[1024];
    int i = blockIdx.x * 1024 + threadIdx.x;
    int c = (i < N_NODES) ? d_cnt_e[i] : 0;
    sh[threadIdx.x] = c;
    __syncthreads();
#pragma unroll
    for (int st = 1; st < 1024; st <<= 1) {
        int v = (threadIdx.x >= st) ? sh[threadIdx.x - st] : 0;
        __syncthreads();
        sh[threadIdx.x] += v;
        __syncthreads();
    }
    if (i < N_NODES) {
        d_off[i] = sh[threadIdx.x] - c;          // exclusive within block
        d_dinv[i] = rsqrtf((float)(c + 1));
    }
    if (threadIdx.x == 1023) d_blk[blockIdx.x] = sh[1023];
}

// final offsets + cursors; each block redundantly scans the 49 block sums in
// shared. Also zeroes pool/gcnt/BN stats.
__global__ __launch_bounds__(256) void k_scan3() {
    __shared__ int shv[64], shs[64];
    int t = threadIdx.x;
    if (t < 64) {
        int v = (t < NBLK_SCAN) ? d_blk[t] : 0;
        shv[t] = v;
        shs[t] = v;
    }
    __syncthreads();
#pragma unroll
    for (int st = 1; st < 64; st <<= 1) {
        int u = (t < 64 && t >= st) ? shs[t - st] : 0;
        __syncthreads();
        if (t < 64) shs[t] += u;
        __syncthreads();
    }

    int i = blockIdx.x * blockDim.x + t;
    if (i < N_NODES) {
        int bb = i >> 10;
        int ex = shs[bb] - shv[bb];              // exclusive prefix
        int o = d_off[i] + ex;
        d_off[i] = o;
        d_pos[i] = o;
    }
    if (blockIdx.x == 0 && t == 0) d_off[N_NODES] = shs[NBLK_SCAN - 1];
    if (i < NGRAPH * HDIM) d_pool[i] = 0.0f;
    if (i < NGRAPH) d_gcnt[i] = 0.0f;
    if (i < 3 * HDIM) { d_sumA[i] = 0.0f; d_sqA[i] = 0.0f; }
}

__global__ void k_scatter(const int* __restrict__ src, const int* __restrict__ dst) {
    int e = blockIdx.x * blockDim.x + threadIdx.x;
    if (e >= N_EDGES) return;
    int s = src[e], d = dst[e];
    float w = d_dinv[s] * d_dinv[d];
    int p = atomicAdd(&d_pos[d], 1);
    d_csr[p] = make_int2(s, __float_as_int(w));
}

// ---------------- fused GEMM ---------------------------------------------------
// Y[N,64] = act(X)[N,64] @ W[64,64]; act = identity (layer 0) or BN-affine+ReLU
// computed inline from layer-(l-1) stats. Output stored as fp16 (d_th).
__global__ __launch_bounds__(256) void k_gemm(const float* __restrict__ Xext,
                                              const float* __restrict__ W,
                                              const float* __restrict__ gp,
                                              const float* __restrict__ bep,
                                              const float* __restrict__ bp,
                                              int layer) {
    __shared__ float Xs[64][68];
    __shared__ float Ws[64][68];
    __shared__ __align__(16) float sh_a[64], sh_c[64];

    const int apply_bn = layer > 0;
    const float* X = apply_bn ? (const float*)d_agg : Xext;

    int tid = threadIdx.x;
    int tx = tid & 15;             // col group (4 cols)
    int ty = tid >> 4;             // row group (4 rows)
    int base = blockIdx.x * 64;

    if (apply_bn && tid < 64) {
        int o = (layer - 1) * 64 + tid;
        float mu  = d_sumA[o] * (1.0f / N_NODES);
        float var = d_sqA[o] * (1.0f / N_NODES) - mu * mu;
        float inv = rsqrtf(var + BN_EPS);
        float a = __ldg(gp + tid) * inv;
        sh_a[tid] = a;
        sh_c[tid] = __ldg(bep + tid) + a * (__ldg(bp + tid) - mu);
    }

    {
        int k = tid >> 4, cg = tid & 15;
#pragma unroll
        for (int i = 0; i < 4; i++) {
            float4 w = ((const float4*)W)[(k + i * 16) * 16 + cg];
            *(float4*)&Ws[k + i * 16][cg * 4] = w;
        }
    }
    __syncthreads();

    {
        int rl = tid >> 4, cg = tid & 15;
        float4 a4 = make_float4(0.f, 0.f, 0.f, 0.f);
        float4 c4 = make_float4(0.f, 0.f, 0.f, 0.f);
        if (apply_bn) {
            a4 = *(const float4*)&sh_a[cg * 4];
            c4 = *(const float4*)&sh_c[cg * 4];
        }
#pragma unroll
        for (int i = 0; i < 4; i++) {
            int row = base + rl + i * 16;
            float4 v = make_float4(0.f, 0.f, 0.f, 0.f);
            if (row < N_NODES) v = ((const float4*)X)[row * 16 + cg];
            if (apply_bn) {
                v.x = fmaxf(0.0f, fmaf(v.x, a4.x, c4.x));
                v.y = fmaxf(0.0f, fmaf(v.y, a4.y, c4.y));
                v.z = fmaxf(0.0f, fmaf(v.z, a4.z, c4.z));
                v.w = fmaxf(0.0f, fmaf(v.w, a4.w, c4.w));
            }
            *(float4*)&Xs[rl + i * 16][cg * 4] = v;
        }
    }
    __syncthreads();

    float acc[4][4];
#pragma unroll
    for (int i = 0; i < 4; i++)
#pragma unroll
        for (int j = 0; j < 4; j++) acc[i][j] = 0.0f;

#pragma unroll
    for (int k4 = 0; k4 < 16; k4++) {
        float4 x0 = *(const float4*)&Xs[ty * 4 + 0][k4 * 4];
        float4 x1 = *(const float4*)&Xs[ty * 4 + 1][k4 * 4];
        float4 x2 = *(const float4*)&Xs[ty * 4 + 2][k4 * 4];
        float4 x3 = *(const float4*)&Xs[ty * 4 + 3][k4 * 4];
#pragma unroll
        for (int kk = 0; kk < 4; kk++) {
            float4 w = *(const float4*)&Ws[k4 * 4 + kk][tx * 4];
            float s0 = ((const float*)&x0)[kk];
            float s1 = ((const float*)&x1)[kk];
            float s2 = ((const float*)&x2)[kk];
            float s3 = ((const float*)&x3)[kk];
            acc[0][0] = fmaf(s0, w.x, acc[0][0]); acc[0][1] = fmaf(s0, w.y, acc[0][1]);
            acc[0][2] = fmaf(s0, w.z, acc[0][2]); acc[0][3] = fmaf(s0, w.w, acc[0][3]);
            acc[1][0] = fmaf(s1, w.x, acc[1][0]); acc[1][1] = fmaf(s1, w.y, acc[1][1]);
            acc[1][2] = fmaf(s1, w.z, acc[1][2]); acc[1][3] = fmaf(s1, w.w, acc[1][3]);
            acc[2][0] = fmaf(s2, w.x, acc[2][0]); acc[2][1] = fmaf(s2, w.y, acc[2][1]);
            acc[2][2] = fmaf(s2, w.z, acc[2][2]); acc[2][3] = fmaf(s2, w.w, acc[2][3]);
            acc[3][0] = fmaf(s3, w.x, acc[3][0]); acc[3][1] = fmaf(s3, w.y, acc[3][1]);
            acc[3][2] = fmaf(s3, w.z, acc[3][2]); acc[3][3] = fmaf(s3, w.w, acc[3][3]);
        }
    }

#pragma unroll
    for (int i = 0; i < 4; i++) {
        int row = base + ty * 4 + i;
        if (row < N_NODES) {
            __half2 h0 = __floats2half2_rn(acc[i][0], acc[i][1]);
            __half2 h1 = __floats2half2_rn(acc[i][2], acc[i][3]);
            uint2 pk;
            pk.x = *(unsigned int*)&h0;
            pk.y = *(unsigned int*)&h1;
            ((uint2*)d_th)[row * 16 + tx] = pk;
        }
    }
}

// ---------------- CSR pull aggregation + fused BN stats ------------------------
// 8 warps/block, each warp handles NPW consecutive nodes (balances degree
// variance). Lanes own 2 columns (half2). Stats in registers, one shared
// reduce per block.
__global__ __launch_bounds__(256) void k_aggregate(const float* __restrict__ b,
                                                   int layer) {
    int tid = threadIdx.x;
    int wid = tid >> 5;
    int lane = tid & 31;
    int node0 = (blockIdx.x * 8 + wid) * NPW;

    __shared__ float sh_s[64], sh_q[64];
    if (tid < 64) { sh_s[tid] = 0.0f; sh_q[tid] = 0.0f; }

    float bx = __ldg(b + lane * 2);
    float by = __ldg(b + lane * 2 + 1);
    float2 ssum = make_float2(0.f, 0.f);
    float2 ssq  = make_float2(0.f, 0.f);

    const __half2* t2 = (const __half2*)d_th;

#pragma unroll 1
    for (int n = 0; n < NPW; n++) {
        int node = node0 + n;
        if (node >= N_NODES) break;
        int beg = d_off[node];
        int end = d_off[node + 1];
        float dv = d_dinv[node];
        float sw = dv * dv;

        float2 self = __half22float2(t2[node * 32 + lane]);
        float2 a0 = make_float2(self.x * sw, self.y * sw);
        float2 a1 = make_float2(0.f, 0.f);
        float2 a2 = make_float2(0.f, 0.f);
        float2 a3 = make_float2(0.f, 0.f);

        int j = beg;
        for (; j + 4 <= end; j += 4) {
            int2 e0 = __ldg(&d_csr[j]);
            int2 e1 = __ldg(&d_csr[j + 1]);
            int2 e2 = __ldg(&d_csr[j + 2]);
            int2 e3 = __ldg(&d_csr[j + 3]);
            float2 v0 = __half22float2(t2[e0.x * 32 + lane]);
            float2 v1 = __half22float2(t2[e1.x * 32 + lane]);
            float2 v2 = __half22float2(t2[e2.x * 32 + lane]);
            float2 v3 = __half22float2(t2[e3.x * 32 + lane]);
            float w0 = __int_as_float(e0.y);
            float w1 = __int_as_float(e1.y);
            float w2 = __int_as_float(e2.y);
            float w3 = __int_as_float(e3.y);
            a0.x = fmaf(w0, v0.x, a0.x); a0.y = fmaf(w0, v0.y, a0.y);
            a1.x = fmaf(w1, v1.x, a1.x); a1.y = fmaf(w1, v1.y, a1.y);
            a2.x = fmaf(w2, v2.x, a2.x); a2.y = fmaf(w2, v2.y, a2.y);
            a3.x = fmaf(w3, v3.x, a3.x); a3.y = fmaf(w3, v3.y, a3.y);
        }
        for (; j < end; j++) {
            int2 e0 = __ldg(&d_csr[j]);
            float2 v0 = __half22float2(t2[e0.x * 32 + lane]);
            float w0 = __int_as_float(e0.y);
            a0.x = fmaf(w0, v0.x, a0.x); a0.y = fmaf(w0, v0.y, a0.y);
        }
        float2 acc;
        acc.x = (a0.x + a1.x) + (a2.x + a3.x);
        acc.y = (a0.y + a1.y) + (a2.y + a3.y);

        ((float2*)d_agg)[node * 32 + lane] = acc;

        float vx = acc.x + bx, vy = acc.y + by;
        ssum.x += vx; ssum.y += vy;
        ssq.x  += vx * vx; ssq.y += vy * vy;
    }

    __syncthreads();
    atomicAdd(&sh_s[lane * 2], ssum.x);
    atomicAdd(&sh_s[lane * 2 + 1], ssum.y);
    atomicAdd(&sh_q[lane * 2], ssq.x);
    atomicAdd(&sh_q[lane * 2 + 1], ssq.y);
    __syncthreads();
    if (tid < 64) {
        atomicAdd(&d_sumA[layer * 64 + tid], sh_s[tid]);
        atomicAdd(&d_sqA[layer * 64 + tid], sh_q[tid]);
    }
}

// ---------------- pooling (fused BN+ReLU of layer 3) + classifier -------------
__global__ __launch_bounds__(256) void k_pool(const int* __restrict__ batch,
                                              const float* __restrict__ gp,
                                              const float* __restrict__ bep,
                                              const float* __restrict__ bp) {
    __shared__ __align__(16) float sh_a[64], sh_c[64];
    int tid = threadIdx.x;
    if (tid < 64) {
        int o = 2 * 64 + tid;
        float mu  = d_sumA[o] * (1.0f / N_NODES);
        float var = d_sqA[o] * (1.0f / N_NODES) - mu * mu;
        float inv = rsqrtf(var + BN_EPS);
        float a = __ldg(gp + tid) * inv;
        sh_a[tid] = a;
        sh_c[tid] = __ldg(bep + tid) + a * (__ldg(bp + tid) - mu);
    }
    __syncthreads();

    int i = blockIdx.x * blockDim.x + tid;   // N*16 chunks
    if (i >= N_NODES * 16) return;
    int node = i >> 4, c = i & 15;
    int g = __ldg(batch + node);
    float4 a4 = *(const float4*)&sh_a[c * 4];
    float4 c4 = *(const float4*)&sh_c[c * 4];
    float4 v = ((const float4*)d_agg)[i];
    v.x = fmaxf(0.0f, fmaf(v.x, a4.x, c4.x));
    v.y = fmaxf(0.0f, fmaf(v.y, a4.y, c4.y));
    v.z = fmaxf(0.0f, fmaf(v.z, a4.z, c4.z));
    v.w = fmaxf(0.0f, fmaf(v.w, a4.w, c4.w));
    float* p = d_pool + (g * 64 + c * 4);
    asm volatile("red.global.add.v4.f32 [%0], {%1,%2,%3,%4};"
                 :: "l"(p), "f"(v.x), "f"(v.y), "f"(v.z), "f"(v.w)
                 : "memory");
    if (c == 0) atomicAdd(&d_gcnt[g], 1.0f);
}

__global__ __launch_bounds__(64) void k_fc(const float* __restrict__ fcW,
                                           const float* __restrict__ fcb,
                                           float* __restrict__ out) {
    int g = blockIdx.x;
    int tid = threadIdx.x;  // 64
    __shared__ float p[64];
    float cnt = fmaxf(d_gcnt[g], 1.0f);
    p[tid] = d_pool[g * 64 + tid] / cnt;
    __syncthreads();
    if (tid < NCLS) {
        float acc = __ldg(fcb + tid);
#pragma unroll
        for (int k = 0; k < 64; k++)
            acc = fmaf(p[k], __ldg(fcW + k * NCLS + tid), acc);
        out[g * NCLS + tid] = acc;
    }
}

// ---------------- launch ------------------------------------------------------
extern "C" void kernel_launch(void* const* d_in, const int* in_sizes, int n_in,
                              void* d_out, int out_size) {
    const float* x     = (const float*)d_in[0];
    const int*   ei    = (const int*)d_in[1];
    const int*   src   = ei;              // edge_index[0]
    const int*   dst   = ei + N_EDGES;    // edge_index[1]
    const int*   batch = (const int*)d_in[2];
    const float* W[3]  = { (const float*)d_in[3],  (const float*)d_in[7],  (const float*)d_in[11] };
    const float* b[3]  = { (const float*)d_in[4],  (const float*)d_in[8],  (const float*)d_in[12] };
    const float* g[3]  = { (const float*)d_in[5],  (const float*)d_in[9],  (const float*)d_in[13] };
    const float* be[3] = { (const float*)d_in[6],  (const float*)d_in[10], (const float*)d_in[14] };
    const float* fcW   = (const float*)d_in[15];
    const float* fcb   = (const float*)d_in[16];
    float* out = (float*)d_out;

    // CSR build (once per call, reused by all 3 layers)
    k_zero_counts<<<(N_NODES + 255) / 256, 256>>>();
    k_hist<<<(N_EDGES + 255) / 256, 256>>>(dst);
    k_scan1<<<NBLK_SCAN, 1024>>>();
    k_scan3<<<(N_NODES + 255) / 256, 256>>>();
    k_scatter<<<(N_EDGES + 255) / 256, 256>>>(src, dst);

    const int gemm_grid = (N_NODES + 63) / 64;
    const int agg_grid = (N_NODES + 8 * NPW - 1) / (8 * NPW);
    for (int l = 0; l < 3; l++) {
        const float* gp  = l > 0 ? g[l - 1]  : g[0];
        const float* bep = l > 0 ? be[l - 1] : be[0];
        const float* bp  = l > 0 ? b[l - 1]  : b[0];
        k_gemm<<<gemm_grid, 256>>>(x, W[l], gp, bep, bp, l);
        k_aggregate<<<agg_grid, 256>>>(b[l], l);
    }

    k_pool<<<(N_NODES * 16 + 255) / 256, 256>>>(batch, g[2], be[2], b[2]);
    k_fc<<<NGRAPH, 64>>>(fcW, fcb, out);
}

// round 9
// speedup vs baseline: 1.9433x; 1.1564x over previous
#include <cuda_runtime.h>
#include <cuda_fp16.h>

#define N_NODES 50000
#define N_EDGES 800000
#define HDIM    64
#define NCLS    6
#define NGRAPH  500
#define BN_EPS  1e-5f
#define NBLK_SCAN ((N_NODES + 1023) / 1024)
#define NPW     8   // nodes per warp in aggregation

// ---------------- scratch (allocation-free: __device__ globals) -------------
__device__ __align__(16) __half d_th[N_NODES * HDIM];   // post-GEMM features (fp16)
__device__ __align__(16) float d_agg[N_NODES * HDIM];   // aggregated features (fp32)
__device__ int   d_cnt_e[N_NODES];          // in-edge counts (zeroed by prev call's scan3 / .bss init)
__device__ int   d_off[N_NODES + 1];        // CSR offsets
__device__ int   d_pos[N_NODES];            // scatter cursors
__device__ int   d_blk[NBLK_SCAN];          // scan block sums
__device__ __align__(8) int2 d_csr[N_EDGES];  // CSR packed (src, w bits)
__device__ float d_dinv[N_NODES];
__device__ float d_sumA[3 * HDIM];          // per-layer BN sum
__device__ float d_sqA[3 * HDIM];           // per-layer BN sumsq
__device__ __align__(16) float d_pool[NGRAPH * HDIM];
__device__ float d_gcnt[NGRAPH];

// ---------------- CSR build ---------------------------------------------------
__global__ void k_hist(const int* __restrict__ dst) {
    int e = blockIdx.x * blockDim.x + threadIdx.x;
    if (e < N_EDGES) atomicAdd(&d_cnt_e[dst[e]], 1);
}

// per-block inclusive scan (coalesced); emits exclusive-in-block offsets + dinv
__global__ __launch_bounds__(1024) void k_scan1() {
    __shared__ int sh[1024];
    int i = blockIdx.x * 1024 + threadIdx.x;
    int c = (i < N_NODES) ? d_cnt_e[i] : 0;
    sh[threadIdx.x] = c;
    __syncthreads();
#pragma unroll
    for (int st = 1; st < 1024; st <<= 1) {
        int v = (threadIdx.x >= st) ? sh[threadIdx.x - st] : 0;
        __syncthreads();
        sh[threadIdx.x] += v;
        __syncthreads();
    }
    if (i < N_NODES) {
        d_off[i] = sh[threadIdx.x] - c;          // exclusive within block
        d_dinv[i] = rsqrtf((float)(c + 1));
    }
    if (threadIdx.x == 1023) d_blk[blockIdx.x] = sh[1023];
}

// final offsets + cursors; each block redundantly scans the 49 block sums in
// shared. Zeroes pool/gcnt/BN stats AND d_cnt_e (for the next execution).
__global__ __launch_bounds__(256) void k_scan3() {
    __shared__ int shv[64], shs[64];
    int t = threadIdx.x;
    if (t < 64) {
        int v = (t < NBLK_SCAN) ? d_blk[t] : 0;
        shv[t] = v;
        shs[t] = v;
    }
    __syncthreads();
#pragma unroll
    for (int st = 1; st < 64; st <<= 1) {
        int u = (t < 64 && t >= st) ? shs[t - st] : 0;
        __syncthreads();
        if (t < 64) shs[t] += u;
        __syncthreads();
    }

    int i = blockIdx.x * blockDim.x + t;
    if (i < N_NODES) {
        int bb = i >> 10;
        int ex = shs[bb] - shv[bb];              // exclusive prefix
        int o = d_off[i] + ex;
        d_off[i] = o;
        d_pos[i] = o;
        d_cnt_e[i] = 0;                          // ready for next execution
    }
    if (blockIdx.x == 0 && t == 0) d_off[N_NODES] = shs[NBLK_SCAN - 1];
    if (i < NGRAPH * HDIM) d_pool[i] = 0.0f;
    if (i < NGRAPH) d_gcnt[i] = 0.0f;
    if (i < 3 * HDIM) { d_sumA[i] = 0.0f; d_sqA[i] = 0.0f; }
}

__global__ void k_scatter(const int* __restrict__ src, const int* __restrict__ dst) {
    int e = blockIdx.x * blockDim.x + threadIdx.x;
    if (e >= N_EDGES) return;
    int s = src[e], d = dst[e];
    float w = d_dinv[s] * d_dinv[d];
    int p = atomicAdd(&d_pos[d], 1);
    d_csr[p] = make_int2(s, __float_as_int(w));
}

// ---------------- tensor-core GEMM ---------------------------------------------
// Y[N,64] = act(X)[N,64] @ W[64,64] via mma.sync m16n8k16 (fp16 in, fp32 accum).
// act = identity (layer 0) or BN-affine+ReLU from layer-(l-1) stats.
// Block: 256 threads = 8 warps; tile 128 rows x 64 cols; warp w owns rows
// [w*16, w*16+16) x all 64 cols (8 n-tiles). K in 4 chunks of 16.
__global__ __launch_bounds__(256) void k_gemm(const float* __restrict__ Xext,
                                              const float* __restrict__ W,
                                              const float* __restrict__ gp,
                                              const float* __restrict__ bep,
                                              const float* __restrict__ bp,
                                              int layer) {
    __shared__ __half Xs[128][72];   // 144B row stride: conflict-free ldmatrix
    __shared__ __half Wsh[64][72];
    __shared__ __align__(16) float sh_a[64], sh_c[64];

    const int apply_bn = layer > 0;
    const float* X = apply_bn ? (const float*)d_agg : Xext;

    int tid = threadIdx.x;
    int base = blockIdx.x * 128;

    if (apply_bn && tid < 64) {
        int o = (layer - 1) * 64 + tid;
        float mu  = d_sumA[o] * (1.0f / N_NODES);
        float var = d_sqA[o] * (1.0f / N_NODES) - mu * mu;
        float inv = rsqrtf(var + BN_EPS);
        float a = __ldg(gp + tid) * inv;
        sh_a[tid] = a;
        sh_c[tid] = __ldg(bep + tid) + a * (__ldg(bp + tid) - mu);
    }

    // stage W[k][n] -> fp16 shared
    {
        int k = tid >> 4, cg = tid & 15;
#pragma unroll
        for (int i = 0; i < 4; i++) {
            float4 w = ((const float4*)W)[(k + i * 16) * 16 + cg];
            __half2 h0 = __floats2half2_rn(w.x, w.y);
            __half2 h1 = __floats2half2_rn(w.z, w.w);
            uint2 pk;
            pk.x = *(unsigned int*)&h0;
            pk.y = *(unsigned int*)&h1;
            *(uint2*)&Wsh[k + i * 16][cg * 4] = pk;
        }
    }
    __syncthreads();  // sh_a/sh_c ready before X staging uses them

    // stage X tile -> fp16 shared (with optional fused BN-affine + ReLU)
    {
        int rl = tid >> 4, cg = tid & 15;
        float4 a4 = make_float4(0.f, 0.f, 0.f, 0.f);
        float4 c4 = make_float4(0.f, 0.f, 0.f, 0.f);
        if (apply_bn) {
            a4 = *(const float4*)&sh_a[cg * 4];
            c4 = *(const float4*)&sh_c[cg * 4];
        }
#pragma unroll
        for (int i = 0; i < 8; i++) {
            int row = base + rl + i * 16;
            float4 v = make_float4(0.f, 0.f, 0.f, 0.f);
            if (row < N_NODES) v = ((const float4*)X)[row * 16 + cg];
            if (apply_bn) {
                v.x = fmaxf(0.0f, fmaf(v.x, a4.x, c4.x));
                v.y = fmaxf(0.0f, fmaf(v.y, a4.y, c4.y));
                v.z = fmaxf(0.0f, fmaf(v.z, a4.z, c4.z));
                v.w = fmaxf(0.0f, fmaf(v.w, a4.w, c4.w));
            }
            __half2 h0 = __floats2half2_rn(v.x, v.y);
            __half2 h1 = __floats2half2_rn(v.z, v.w);
            uint2 pk;
            pk.x = *(unsigned int*)&h0;
            pk.y = *(unsigned int*)&h1;
            *(uint2*)&Xs[rl + i * 16][cg * 4] = pk;
        }
    }
    __syncthreads();

    int w = tid >> 5, lane = tid & 31;
    int row0 = w * 16;

    float c[8][4];
#pragma unroll
    for (int n = 0; n < 8; n++)
#pragma unroll
        for (int j = 0; j < 4; j++) c[n][j] = 0.0f;

#pragma unroll
    for (int kc = 0; kc < 4; kc++) {
        // A fragment: m16k16 from Xs
        unsigned int a0, a1, a2, a3;
        {
            const __half* p = &Xs[row0 + (lane & 15)][kc * 16 + (lane >> 4) * 8];
            unsigned int addr = (unsigned int)__cvta_generic_to_shared(p);
            asm volatile("ldmatrix.sync.aligned.m8n8.x4.shared.b16 {%0,%1,%2,%3}, [%4];"
                         : "=r"(a0), "=r"(a1), "=r"(a2), "=r"(a3) : "r"(addr));
        }
        // B fragments: k16 x n16 per ldmatrix.x4.trans (2 n-tiles)
#pragma unroll
        for (int np = 0; np < 4; np++) {
            unsigned int b0, b1, b2, b3;
            const __half* p = &Wsh[kc * 16 + (lane & 15)][np * 16 + (lane >> 4) * 8];
            unsigned int addr = (unsigned int)__cvta_generic_to_shared(p);
            asm volatile("ldmatrix.sync.aligned.m8n8.x4.trans.shared.b16 {%0,%1,%2,%3}, [%4];"
                         : "=r"(b0), "=r"(b1), "=r"(b2), "=r"(b3) : "r"(addr));
            int nt0 = np * 2, nt1 = np * 2 + 1;
            asm volatile("mma.sync.aligned.m16n8k16.row.col.f32.f16.f16.f32 "
                         "{%0,%1,%2,%3}, {%4,%5,%6,%7}, {%8,%9}, {%0,%1,%2,%3};"
                         : "+f"(c[nt0][0]), "+f"(c[nt0][1]), "+f"(c[nt0][2]), "+f"(c[nt0][3])
                         : "r"(a0), "r"(a1), "r"(a2), "r"(a3), "r"(b0), "r"(b1));
            asm volatile("mma.sync.aligned.m16n8k16.row.col.f32.f16.f16.f32 "
                         "{%0,%1,%2,%3}, {%4,%5,%6,%7}, {%8,%9}, {%0,%1,%2,%3};"
                         : "+f"(c[nt1][0]), "+f"(c[nt1][1]), "+f"(c[nt1][2]), "+f"(c[nt1][3])
                         : "r"(a0), "r"(a1), "r"(a2), "r"(a3), "r"(b2), "r"(b3));
        }
    }

    // epilogue: fp16 stores. c[nt][0..1] -> row r0, cols col..col+1;
    //           c[nt][2..3] -> row r0+8.
    int r0 = base + row0 + (lane >> 2);
    int r1 = r0 + 8;
    bool ok0 = r0 < N_NODES, ok1 = r1 < N_NODES;
#pragma unroll
    for (int nt = 0; nt < 8; nt++) {
        int col = nt * 8 + (lane & 3) * 2;
        if (ok0) {
            __half2 h = __floats2half2_rn(c[nt][0], c[nt][1]);
            *(__half2*)&d_th[r0 * 64 + col] = h;
        }
        if (ok1) {
            __half2 h = __floats2half2_rn(c[nt][2], c[nt][3]);
            *(__half2*)&d_th[r1 * 64 + col] = h;
        }
    }
}

// ---------------- CSR pull aggregation + fused BN stats ------------------------
// 8 warps/block, each warp handles NPW consecutive nodes. Lanes own 2 columns
// (half2). Stats in registers, one shared reduce per block.
__global__ __launch_bounds__(256) void k_aggregate(const float* __restrict__ b,
                                                   int layer) {
    int tid = threadIdx.x;
    int wid = tid >> 5;
    int lane = tid & 31;
    int node0 = (blockIdx.x * 8 + wid) * NPW;

    __shared__ float sh_s[64], sh_q[64];
    if (tid < 64) { sh_s[tid] = 0.0f; sh_q[tid] = 0.0f; }

    float bx = __ldg(b + lane * 2);
    float by = __ldg(b + lane * 2 + 1);
    float2 ssum = make_float2(0.f, 0.f);
    float2 ssq  = make_float2(0.f, 0.f);

    const __half2* t2 = (const __half2*)d_th;

#pragma unroll 1
    for (int n = 0; n < NPW; n++) {
        int node = node0 + n;
        if (node >= N_NODES) break;
        int beg = d_off[node];
        int end = d_off[node + 1];
        float dv = d_dinv[node];
        float sw = dv * dv;

        float2 self = __half22float2(t2[node * 32 + lane]);
        float2 a0 = make_float2(self.x * sw, self.y * sw);
        float2 a1 = make_float2(0.f, 0.f);
        float2 a2 = make_float2(0.f, 0.f);
        float2 a3 = make_float2(0.f, 0.f);

        int j = beg;
        for (; j + 4 <= end; j += 4) {
            int2 e0 = __ldg(&d_csr[j]);
            int2 e1 = __ldg(&d_csr[j + 1]);
            int2 e2 = __ldg(&d_csr[j + 2]);
            int2 e3 = __ldg(&d_csr[j + 3]);
            float2 v0 = __half22float2(t2[e0.x * 32 + lane]);
            float2 v1 = __half22float2(t2[e1.x * 32 + lane]);
            float2 v2 = __half22float2(t2[e2.x * 32 + lane]);
            float2 v3 = __half22float2(t2[e3.x * 32 + lane]);
            float w0 = __int_as_float(e0.y);
            float w1 = __int_as_float(e1.y);
            float w2 = __int_as_float(e2.y);
            float w3 = __int_as_float(e3.y);
            a0.x = fmaf(w0, v0.x, a0.x); a0.y = fmaf(w0, v0.y, a0.y);
            a1.x = fmaf(w1, v1.x, a1.x); a1.y = fmaf(w1, v1.y, a1.y);
            a2.x = fmaf(w2, v2.x, a2.x); a2.y = fmaf(w2, v2.y, a2.y);
            a3.x = fmaf(w3, v3.x, a3.x); a3.y = fmaf(w3, v3.y, a3.y);
        }
        for (; j < end; j++) {
            int2 e0 = __ldg(&d_csr[j]);
            float2 v0 = __half22float2(t2[e0.x * 32 + lane]);
            float w0 = __int_as_float(e0.y);
            a0.x = fmaf(w0, v0.x, a0.x); a0.y = fmaf(w0, v0.y, a0.y);
        }
        float2 acc;
        acc.x = (a0.x + a1.x) + (a2.x + a3.x);
        acc.y = (a0.y + a1.y) + (a2.y + a3.y);

        ((float2*)d_agg)[node * 32 + lane] = acc;

        float vx = acc.x + bx, vy = acc.y + by;
        ssum.x += vx; ssum.y += vy;
        ssq.x  += vx * vx; ssq.y += vy * vy;
    }

    __syncthreads();
    atomicAdd(&sh_s[lane * 2], ssum.x);
    atomicAdd(&sh_s[lane * 2 + 1], ssum.y);
    atomicAdd(&sh_q[lane * 2], ssq.x);
    atomicAdd(&sh_q[lane * 2 + 1], ssq.y);
    __syncthreads();
    if (tid < 64) {
        atomicAdd(&d_sumA[layer * 64 + tid], sh_s[tid]);
        atomicAdd(&d_sqA[layer * 64 + tid], sh_q[tid]);
    }
}

// ---------------- pooling (fused BN+ReLU of layer 3) + classifier -------------
__global__ __launch_bounds__(256) void k_pool(const int* __restrict__ batch,
                                              const float* __restrict__ gp,
                                              const float* __restrict__ bep,
                                              const float* __restrict__ bp) {
    __shared__ __align__(16) float sh_a[64], sh_c[64];
    int tid = threadIdx.x;
    if (tid < 64) {
        int o = 2 * 64 + tid;
        float mu  = d_sumA[o] * (1.0f / N_NODES);
        float var = d_sqA[o] * (1.0f / N_NODES) - mu * mu;
        float inv = rsqrtf(var + BN_EPS);
        float a = __ldg(gp + tid) * inv;
        sh_a[tid] = a;
        sh_c[tid] = __ldg(bep + tid) + a * (__ldg(bp + tid) - mu);
    }
    __syncthreads();

    int i = blockIdx.x * blockDim.x + tid;   // N*16 chunks
    if (i >= N_NODES * 16) return;
    int node = i >> 4, c = i & 15;
    int g = __ldg(batch + node);
    float4 a4 = *(const float4*)&sh_a[c * 4];
    float4 c4 = *(const float4*)&sh_c[c * 4];
    float4 v = ((const float4*)d_agg)[i];
    v.x = fmaxf(0.0f, fmaf(v.x, a4.x, c4.x));
    v.y = fmaxf(0.0f, fmaf(v.y, a4.y, c4.y));
    v.z = fmaxf(0.0f, fmaf(v.z, a4.z, c4.z));
    v.w = fmaxf(0.0f, fmaf(v.w, a4.w, c4.w));
    float* p = d_pool + (g * 64 + c * 4);
    asm volatile("red.global.add.v4.f32 [%0], {%1,%2,%3,%4};"
                 :: "l"(p), "f"(v.x), "f"(v.y), "f"(v.z), "f"(v.w)
                 : "memory");
    if (c == 0) atomicAdd(&d_gcnt[g], 1.0f);
}

__global__ __launch_bounds__(64) void k_fc(const float* __restrict__ fcW,
                                           const float* __restrict__ fcb,
                                           float* __restrict__ out) {
    int g = blockIdx.x;
    int tid = threadIdx.x;  // 64
    __shared__ float p[64];
    float cnt = fmaxf(d_gcnt[g], 1.0f);
    p[tid] = d_pool[g * 64 + tid] / cnt;
    __syncthreads();
    if (tid < NCLS) {
        float acc = __ldg(fcb + tid);
#pragma unroll
        for (int k = 0; k < 64; k++)
            acc = fmaf(p[k], __ldg(fcW + k * NCLS + tid), acc);
        out[g * NCLS + tid] = acc;
    }
}

// ---------------- launch ------------------------------------------------------
extern "C" void kernel_launch(void* const* d_in, const int* in_sizes, int n_in,
                              void* d_out, int out_size) {
    const float* x     = (const float*)d_in[0];
    const int*   ei    = (const int*)d_in[1];
    const int*   src   = ei;              // edge_index[0]
    const int*   dst   = ei + N_EDGES;    // edge_index[1]
    const int*   batch = (const int*)d_in[2];
    const float* W[3]  = { (const float*)d_in[3],  (const float*)d_in[7],  (const float*)d_in[11] };
    const float* b[3]  = { (const float*)d_in[4],  (const float*)d_in[8],  (const float*)d_in[12] };
    const float* g[3]  = { (const float*)d_in[5],  (const float*)d_in[9],  (const float*)d_in[13] };
    const float* be[3] = { (const float*)d_in[6],  (const float*)d_in[10], (const float*)d_in[14] };
    const float* fcW   = (const float*)d_in[15];
    const float* fcb   = (const float*)d_in[16];
    float* out = (float*)d_out;

    // CSR build (counts arrive zeroed: .bss init on first run, scan3 thereafter)
    k_hist<<<(N_EDGES + 255) / 256, 256>>>(dst);
    k_scan1<<<NBLK_SCAN, 1024>>>();
    k_scan3<<<(N_NODES + 255) / 256, 256>>>();
    k_scatter<<<(N_EDGES + 255) / 256, 256>>>(src, dst);

    const int gemm_grid = (N_NODES + 127) / 128;
    const int agg_grid = (N_NODES + 8 * NPW - 1) / (8 * NPW);
    for (int l = 0; l < 3; l++) {
        const float* gp  = l > 0 ? g[l - 1]  : g[0];
        const float* bep = l > 0 ? be[l - 1] : be[0];
        const float* bp  = l > 0 ? b[l - 1]  : b[0];
        k_gemm<<<gemm_grid, 256>>>(x, W[l], gp, bep, bp, l);
        k_aggregate<<<agg_grid, 256>>>(b[l], l);
    }

    k_pool<<<(N_NODES * 16 + 255) / 256, 256>>>(batch, g[2], be[2], b[2]);
    k_fc<<<NGRAPH, 64>>>(fcW, fcb, out);
}